// round 10
// baseline (speedup 1.0000x reference)
#include <cuda_runtime.h>
#include <cuda_bf16.h>
#include <cstdint>
#include <math.h>

#define S    3072
#define DIM  1280
#define NH   16
#define HD   80
#define SEG  512
#define NSEG 6

// ---------------- scratch (__device__ globals; no allocs allowed) ----------
__device__ float g_q[S * DIM];
__device__ float g_k[S * DIM];
__device__ float g_v[S * DIM];

__device__ __nv_bfloat16 g_ah[S * DIM];
__device__ __nv_bfloat16 g_al[S * DIM];
__device__ __nv_bfloat16 g_wh[4 * DIM * DIM];
__device__ __nv_bfloat16 g_wl[4 * DIM * DIM];
__device__ __nv_bfloat16 g_ch[S * DIM];
__device__ __nv_bfloat16 g_cl[S * DIM];

__device__ __nv_bfloat16 g_qh[NH * S * HD];
__device__ __nv_bfloat16 g_ql[NH * S * HD];
__device__ __nv_bfloat16 g_kh[NH * S * HD];
__device__ __nv_bfloat16 g_kl[NH * S * HD];
__device__ __nv_bfloat16 g_vh[NH * S * HD];
__device__ __nv_bfloat16 g_vl[NH * S * HD];

// ---------------- PTX helpers (sm_80-era, arch-neutral) --------------------
__device__ __forceinline__ uint32_t smem_u32(const void* p) {
    uint32_t a;
    asm("{ .reg .u64 t; cvta.to.shared.u64 t, %1; cvt.u32.u64 %0, t; }"
        : "=r"(a) : "l"(p));
    return a;
}
__device__ __forceinline__ void ldsm4(uint32_t* r, uint32_t addr) {
    asm volatile("ldmatrix.sync.aligned.m8n8.x4.shared.b16 {%0,%1,%2,%3}, [%4];"
                 : "=r"(r[0]), "=r"(r[1]), "=r"(r[2]), "=r"(r[3]) : "r"(addr));
}
__device__ __forceinline__ void ldsm4t(uint32_t* r, uint32_t addr) {
    asm volatile("ldmatrix.sync.aligned.m8n8.x4.trans.shared.b16 {%0,%1,%2,%3}, [%4];"
                 : "=r"(r[0]), "=r"(r[1]), "=r"(r[2]), "=r"(r[3]) : "r"(addr));
}
__device__ __forceinline__ void mma16816(float* d, const uint32_t* a, const uint32_t* b) {
    asm volatile(
        "mma.sync.aligned.m16n8k16.row.col.f32.bf16.bf16.f32 "
        "{%0,%1,%2,%3}, {%4,%5,%6,%7}, {%8,%9}, {%0,%1,%2,%3};"
        : "+f"(d[0]), "+f"(d[1]), "+f"(d[2]), "+f"(d[3])
        : "r"(a[0]), "r"(a[1]), "r"(a[2]), "r"(a[3]), "r"(b[0]), "r"(b[1]));
}

#define CP_ASYNC16(dst, src) \
    asm volatile("cp.async.cg.shared.global [%0], [%1], 16;" :: "r"(dst), "l"(src))
#define CP_COMMIT() asm volatile("cp.async.commit_group;")
#define CP_WAIT3()  asm volatile("cp.async.wait_group 3;")
#define CP_WAIT2()  asm volatile("cp.async.wait_group 2;")
#define CP_WAIT1()  asm volatile("cp.async.wait_group 1;")
#define CP_WAIT0()  asm volatile("cp.async.wait_group 0;")

// pack two fp32 into bf16x2 hi, return hi bits, set lo bits
__device__ __forceinline__ uint32_t pk2(float x, float y, uint32_t& lo) {
    __nv_bfloat162 h, l;
    h.x = __float2bfloat16(x); h.y = __float2bfloat16(y);
    l.x = __float2bfloat16(x - __bfloat162float(h.x));
    l.y = __float2bfloat16(y - __bfloat162float(h.y));
    lo = *(uint32_t*)&l;
    return *(uint32_t*)&h;
}

// ---------------- fp32 -> bf16 hi/lo split (vectorized) ---------------------
__device__ __forceinline__ void split4(float4 v, uint2& ho, uint2& lo) {
    uint32_t l0, l1;
    uint32_t h0 = pk2(v.x, v.y, l0);
    uint32_t h1 = pk2(v.z, v.w, l1);
    ho = make_uint2(h0, h1);
    lo = make_uint2(l0, l1);
}

__global__ void split_hs(const float4* __restrict__ src,
                         uint2* __restrict__ hi, uint2* __restrict__ lo, int n4) {
    int i = blockIdx.x * blockDim.x + threadIdx.x;
    if (i < n4) {
        uint2 h, l;
        split4(src[i], h, l);
        hi[i] = h; lo[i] = l;
    }
}

__global__ void split_w4(const float4* __restrict__ s0, const float4* __restrict__ s1,
                         const float4* __restrict__ s2, const float4* __restrict__ s3,
                         uint2* __restrict__ hi, uint2* __restrict__ lo) {
    int z = blockIdx.y;
    const float4* s = (z == 0) ? s0 : (z == 1) ? s1 : (z == 2) ? s2 : s3;
    size_t base = (size_t)z * (DIM * DIM / 4);
    int i = blockIdx.x * blockDim.x + threadIdx.x;
    uint2 h, l;
    split4(s[i], h, l);
    hi[base + i] = h; lo[base + i] = l;
}

// ---------------- HMMA bf16x3 GEMM ------------------------------------------
#define GBM 128
#define GBN 128
#define NCHUNK (DIM / 32)
#define TSTRIDE 80
#define TILE_B  (128 * TSTRIDE)
#define STAGE_B (4 * TILE_B)
#define GEMM_SMEM (2 * STAGE_B)

__global__ __launch_bounds__(256, 2) void gemm_hmma(
    const __nv_bfloat16* __restrict__ Ahi, const __nv_bfloat16* __restrict__ Alo,
    const __nv_bfloat16* __restrict__ Whi_base, const __nv_bfloat16* __restrict__ Wlo_base,
    int zoff,
    const float* __restrict__ bias0, const float* __restrict__ bias1, const float* __restrict__ bias2,
    float* __restrict__ C0, float* __restrict__ C1, float* __restrict__ C2)
{
    extern __shared__ char smem[];
    const uint32_t sb = smem_u32(smem);
    const int tid  = threadIdx.x;
    const int wid  = tid >> 5;
    const int lane = tid & 31;

    const int z = blockIdx.z;
    const __nv_bfloat16* Wh = Whi_base + (size_t)(zoff + z) * DIM * DIM;
    const __nv_bfloat16* Wl = Wlo_base + (size_t)(zoff + z) * DIM * DIM;
    const float* bias = (z == 0) ? bias0 : (z == 1) ? bias1 : bias2;
    float* C = (z == 0) ? C0 : (z == 1) ? C1 : C2;

    const int m0 = blockIdx.y * GBM;
    const int n0 = blockIdx.x * GBN;
    const int wm = (wid & 1) * 64;
    const int wn = (wid >> 1) * 32;

    const int tile = tid >> 6;
    const int t64  = tid & 63;
    const char* gsrc;
    if (tile == 0)      gsrc = (const char*)(Ahi + (size_t)m0 * DIM);
    else if (tile == 1) gsrc = (const char*)(Alo + (size_t)m0 * DIM);
    else if (tile == 2) gsrc = (const char*)(Wh  + (size_t)n0 * DIM);
    else                gsrc = (const char*)(Wl  + (size_t)n0 * DIM);
    const uint32_t sdst0 = sb + tile * TILE_B;

    float acc[4][4][4];
#pragma unroll
    for (int mt = 0; mt < 4; mt++)
#pragma unroll
        for (int nt = 0; nt < 4; nt++)
#pragma unroll
            for (int i = 0; i < 4; i++) acc[mt][nt][i] = 0.f;

    {
        const char* s = gsrc;
        uint32_t d = sdst0;
#pragma unroll
        for (int i = 0; i < 8; i++) {
            int idx = i * 64 + t64;
            int row = idx >> 2, c16 = idx & 3;
            CP_ASYNC16(d + row * TSTRIDE + c16 * 16,
                       s + (size_t)row * (DIM * 2) + c16 * 16);
        }
        CP_COMMIT();
    }

    const int arow = lane & 15;
    const int acolh = (lane >> 4) * 16;
    const int browa = ((lane >> 4) << 3) + (lane & 7);
    const int bcolh = ((lane >> 3) & 1) * 16;

    for (int c = 0; c < NCHUNK; c++) {
        if (c + 1 < NCHUNK) {
            const char* s = gsrc + (size_t)(c + 1) * 64;
            uint32_t d = sdst0 + ((c + 1) & 1) * STAGE_B;
#pragma unroll
            for (int i = 0; i < 8; i++) {
                int idx = i * 64 + t64;
                int row = idx >> 2, c16 = idx & 3;
                CP_ASYNC16(d + row * TSTRIDE + c16 * 16,
                           s + (size_t)row * (DIM * 2) + c16 * 16);
            }
            CP_COMMIT();
            CP_WAIT1();
        } else {
            CP_WAIT0();
        }
        __syncthreads();

        const uint32_t stage = sb + (c & 1) * STAGE_B;
        const uint32_t sAh = stage;
        const uint32_t sAl = stage + TILE_B;
        const uint32_t sWh = stage + 2 * TILE_B;
        const uint32_t sWl = stage + 3 * TILE_B;

#pragma unroll
        for (int ks = 0; ks < 2; ks++) {
            const int acol = ks * 32 + acolh;
            uint32_t bh[8], bl[8];
            {
                uint32_t boff = (uint32_t)((wn + browa) * TSTRIDE + ks * 32 + bcolh);
                ldsm4(bh,     sWh + boff);
                ldsm4(bh + 4, sWh + boff + 16 * TSTRIDE);
                ldsm4(bl,     sWl + boff);
                ldsm4(bl + 4, sWl + boff + 16 * TSTRIDE);
            }
            // software-pipelined A frags: prefetch mt+1 before mt's MMAs
            uint32_t ahb[2][4], alb[2][4];
            {
                uint32_t off0 = (uint32_t)((wm + arow) * TSTRIDE + acol);
                ldsm4(ahb[0], sAh + off0);
                ldsm4(alb[0], sAl + off0);
            }
#pragma unroll
            for (int mt = 0; mt < 4; mt++) {
                const int cur = mt & 1;
                if (mt < 3) {
                    uint32_t off = (uint32_t)((wm + (mt + 1) * 16 + arow) * TSTRIDE + acol);
                    ldsm4(ahb[cur ^ 1], sAh + off);
                    ldsm4(alb[cur ^ 1], sAl + off);
                }
#pragma unroll
                for (int nt = 0; nt < 4; nt++) {
                    mma16816(acc[mt][nt], ahb[cur], bh + nt * 2);
                    mma16816(acc[mt][nt], ahb[cur], bl + nt * 2);
                    mma16816(acc[mt][nt], alb[cur], bh + nt * 2);
                }
            }
        }
        __syncthreads();
    }

    const int r0 = lane >> 2;
    const int c0 = (lane & 3) * 2;
#pragma unroll
    for (int mt = 0; mt < 4; mt++) {
#pragma unroll
        for (int nt = 0; nt < 4; nt++) {
            int gm = m0 + wm + mt * 16 + r0;
            int gn = n0 + wn + nt * 8 + c0;
            float2 bv = *(const float2*)(bias + gn);
            float2 o0, o1;
            o0.x = acc[mt][nt][0] + bv.x;
            o0.y = acc[mt][nt][1] + bv.y;
            o1.x = acc[mt][nt][2] + bv.x;
            o1.y = acc[mt][nt][3] + bv.y;
            *(float2*)(C + (size_t)gm * DIM + gn) = o0;
            *(float2*)(C + (size_t)(gm + 8) * DIM + gn) = o1;
        }
    }
}

// ---------------- pack: rope + scale + split + per-head relayout ------------
__global__ void pack_qkv(const float* __restrict__ cosb,
                         const float* __restrict__ sinb)
{
    const int s = blockIdx.x;
    const int tid = threadIdx.x;
    const float scale = 0.11180339887498949f;

    for (int p = tid; p < NH * 20; p += 256) {
        int h = p / 20, dp = (p % 20) * 2;
        float2 c2 = *(const float2*)(cosb + s * HD + dp);
        float2 s2 = *(const float2*)(sinb + s * HD + dp);
        size_t ib = (size_t)s * DIM + h * HD + dp;
        size_t ob = ((size_t)h * S + s) * HD + dp;

        float2 qa = *(const float2*)(g_q + ib);
        float2 qb = *(const float2*)(g_q + ib + 40);
        float q1x = (qa.x * c2.x - qb.x * s2.x) * scale;
        float q1y = (qa.y * c2.y - qb.y * s2.y) * scale;
        float q2x = (qb.x * c2.x + qa.x * s2.x) * scale;
        float q2y = (qb.y * c2.y + qa.y * s2.y) * scale;
        uint32_t lo, hi;
        hi = pk2(q1x, q1y, lo);
        *(uint32_t*)(g_qh + ob) = hi;      *(uint32_t*)(g_ql + ob) = lo;
        hi = pk2(q2x, q2y, lo);
        *(uint32_t*)(g_qh + ob + 40) = hi; *(uint32_t*)(g_ql + ob + 40) = lo;

        float2 ka = *(const float2*)(g_k + ib);
        float2 kb = *(const float2*)(g_k + ib + 40);
        float k1x = ka.x * c2.x - kb.x * s2.x;
        float k1y = ka.y * c2.y - kb.y * s2.y;
        float k2x = kb.x * c2.x + ka.x * s2.x;
        float k2y = kb.y * c2.y + ka.y * s2.y;
        hi = pk2(k1x, k1y, lo);
        *(uint32_t*)(g_kh + ob) = hi;      *(uint32_t*)(g_kl + ob) = lo;
        hi = pk2(k2x, k2y, lo);
        *(uint32_t*)(g_kh + ob + 40) = hi; *(uint32_t*)(g_kl + ob + 40) = lo;
    }

    for (int p = tid; p < DIM / 2; p += 256) {
        int e = p * 2;
        int h = e / HD, d = e % HD;
        float2 v2 = *(const float2*)(g_v + (size_t)s * DIM + e);
        size_t ob = ((size_t)h * S + s) * HD + d;
        uint32_t lo, hi;
        hi = pk2(v2.x, v2.y, lo);
        *(uint32_t*)(g_vh + ob) = hi;
        *(uint32_t*)(g_vl + ob) = lo;
    }
}

// ---------------- flash attention: register S/P, double-buffered KV ---------
#define ATS 176
#define ATB (64 * ATS)
#define AQH 0
#define AQL ATB
#define AKV0 (2 * ATB)
#define AKV1 (6 * ATB)
#define APMAX (10 * ATB)
#define APLS  (APMAX + 512)
#define ATTN_SMEM (APLS + 256)        // 113408 B

__global__ __launch_bounds__(256, 2) void attn_mma(__nv_bfloat16* __restrict__ ch,
                                                   __nv_bfloat16* __restrict__ cl)
{
    extern __shared__ char sm[];
    const uint32_t sb = smem_u32(sm);
    const int tid = threadIdx.x;
    const int wid = tid >> 5;
    const int lane = tid & 31;

    const int qt = blockIdx.x;
    const int h  = blockIdx.y;
    const int sg = blockIdx.z;
    const int s0 = sg * SEG;
    const int q0 = s0 + qt * 64;
    const size_t hb = (size_t)h * S * HD;

    const int wm = (wid & 3) * 16;
    const int wh = wid >> 2;
    const int wn = wh * 32;

    float* pmax = (float*)(sm + APMAX);
    float* plsum = (float*)(sm + APLS);

    const char* qhp = (const char*)(g_qh + hb + (size_t)q0 * HD);
    const char* qlp = (const char*)(g_ql + hb + (size_t)q0 * HD);
    const char* khp = (const char*)(g_kh + hb + (size_t)s0 * HD);
    const char* klp = (const char*)(g_kl + hb + (size_t)s0 * HD);
    const char* vhp = (const char*)(g_vh + hb + (size_t)s0 * HD);
    const char* vlp = (const char*)(g_vl + hb + (size_t)s0 * HD);

    auto cp_pair = [&](uint32_t dH, uint32_t dL, const char* srcH, const char* srcL, int rb) {
#pragma unroll
        for (int i = 0; i < 5; i++) {
            int f = i * 256 + tid;
            int sel = f >= 640;
            int g = f - (sel ? 640 : 0);
            int r = g / 10, c = g - r * 10;
            CP_ASYNC16(sb + (sel ? dL : dH) + r * ATS + c * 16,
                       (sel ? srcL : srcH) + (size_t)(rb + r) * 160 + c * 16);
        }
    };

    cp_pair(AQH, AQL, qhp, qlp, 0);
    cp_pair(AKV0, AKV0 + ATB, khp, klp, 0);
    CP_COMMIT();
    cp_pair(AKV0 + 2 * ATB, AKV0 + 3 * ATB, vhp, vlp, 0);
    CP_COMMIT();
    cp_pair(AKV1, AKV1 + ATB, khp, klp, 64);
    CP_COMMIT();
    cp_pair(AKV1 + 2 * ATB, AKV1 + 3 * ATB, vhp, vlp, 64);
    CP_COMMIT();

    float acc[10][4];
#pragma unroll
    for (int nt = 0; nt < 10; nt++)
#pragma unroll
        for (int i = 0; i < 4; i++) acc[nt][i] = 0.f;

    float mold0 = -1e30f, mold1 = -1e30f;
    float lsum0 = 0.f, lsum1 = 0.f;

    const int qrow = wm + (lane & 15);
    const uint32_t qcoloff = (uint32_t)((lane >> 4) * 16);
    const int krowa = wn + ((lane >> 4) << 3) + (lane & 7);
    const uint32_t kcoloff = (uint32_t)(((lane >> 3) & 1) * 16);
    const int r4 = lane >> 2;
    const int q2 = (lane & 3) * 2;

    for (int c = 0; c < 8; c++) {
        const uint32_t kv = sb + ((c & 1) ? AKV1 : AKV0);
        const uint32_t sKH = kv, sKL = kv + ATB, sVH = kv + 2 * ATB, sVL = kv + 3 * ATB;

        if (c == 7) { CP_WAIT1(); } else { CP_WAIT3(); }
        __syncthreads();

        float sa[4][4];
#pragma unroll
        for (int nt = 0; nt < 4; nt++)
#pragma unroll
            for (int i = 0; i < 4; i++) sa[nt][i] = 0.f;

#pragma unroll
        for (int ks = 0; ks < 5; ks++) {
            uint32_t qh4[4], ql4[4], kh[8], kl[8];
            uint32_t qoff = (uint32_t)(qrow * ATS + ks * 32) + qcoloff;
            ldsm4(qh4, sb + AQH + qoff);
            ldsm4(ql4, sb + AQL + qoff);
            uint32_t koff0 = (uint32_t)(krowa * ATS + ks * 32) + kcoloff;
            ldsm4(kh,     sKH + koff0);
            ldsm4(kh + 4, sKH + koff0 + 16 * ATS);
            ldsm4(kl,     sKL + koff0);
            ldsm4(kl + 4, sKL + koff0 + 16 * ATS);
#pragma unroll
            for (int nt = 0; nt < 4; nt++) {
                mma16816(sa[nt], qh4, kh + nt * 2);
                mma16816(sa[nt], qh4, kl + nt * 2);
                mma16816(sa[nt], ql4, kh + nt * 2);
            }
        }

        float mx0 = fmaxf(fmaxf(sa[0][0], sa[0][1]), fmaxf(sa[1][0], sa[1][1]));
        mx0 = fmaxf(mx0, fmaxf(fmaxf(sa[2][0], sa[2][1]), fmaxf(sa[3][0], sa[3][1])));
        float mx1 = fmaxf(fmaxf(sa[0][2], sa[0][3]), fmaxf(sa[1][2], sa[1][3]));
        mx1 = fmaxf(mx1, fmaxf(fmaxf(sa[2][2], sa[2][3]), fmaxf(sa[3][2], sa[3][3])));
        mx0 = fmaxf(mx0, __shfl_xor_sync(0xffffffffu, mx0, 1));
        mx0 = fmaxf(mx0, __shfl_xor_sync(0xffffffffu, mx0, 2));
        mx1 = fmaxf(mx1, __shfl_xor_sync(0xffffffffu, mx1, 1));
        mx1 = fmaxf(mx1, __shfl_xor_sync(0xffffffffu, mx1, 2));
        if ((lane & 3) == 0) {
            pmax[wh * 64 + wm + r4] = mx0;
            pmax[wh * 64 + wm + 8 + r4] = mx1;
        }

        if (c == 7) { CP_WAIT0(); } else { CP_WAIT2(); }
        __syncthreads();

        float ma0 = fmaxf(pmax[wm + r4], pmax[64 + wm + r4]);
        float ma1 = fmaxf(pmax[wm + 8 + r4], pmax[64 + wm + 8 + r4]);
        float mn0 = fmaxf(mold0, ma0);
        float mn1 = fmaxf(mold1, ma1);
        float fs0 = __expf(mold0 - mn0);
        float fs1 = __expf(mold1 - mn1);
        mold0 = mn0; mold1 = mn1;

        float s0r = 0.f, s1r = 0.f;
#pragma unroll
        for (int nt = 0; nt < 4; nt++) {
            sa[nt][0] = __expf(sa[nt][0] - mn0);
            sa[nt][1] = __expf(sa[nt][1] - mn0);
            sa[nt][2] = __expf(sa[nt][2] - mn1);
            sa[nt][3] = __expf(sa[nt][3] - mn1);
            s0r += sa[nt][0] + sa[nt][1];
            s1r += sa[nt][2] + sa[nt][3];
        }
        s0r += __shfl_xor_sync(0xffffffffu, s0r, 1);
        s0r += __shfl_xor_sync(0xffffffffu, s0r, 2);
        s1r += __shfl_xor_sync(0xffffffffu, s1r, 1);
        s1r += __shfl_xor_sync(0xffffffffu, s1r, 2);
        lsum0 = lsum0 * fs0 + s0r;
        lsum1 = lsum1 * fs1 + s1r;

#pragma unroll
        for (int nt = 0; nt < 10; nt++) {
            acc[nt][0] *= fs0; acc[nt][1] *= fs0;
            acc[nt][2] *= fs1; acc[nt][3] *= fs1;
        }

#pragma unroll
        for (int kb = 0; kb < 2; kb++) {
            uint32_t aH[4], aL[4];
            aH[0] = pk2(sa[2 * kb][0], sa[2 * kb][1], aL[0]);
            aH[1] = pk2(sa[2 * kb][2], sa[2 * kb][3], aL[1]);
            aH[2] = pk2(sa[2 * kb + 1][0], sa[2 * kb + 1][1], aL[2]);
            aH[3] = pk2(sa[2 * kb + 1][2], sa[2 * kb + 1][3], aL[3]);
            const int vrow = wn + kb * 16 + (lane & 15);
#pragma unroll
            for (int np = 0; np < 5; np++) {
                uint32_t vh4[4], vl4[4];
                uint32_t voff = (uint32_t)(vrow * ATS + (np * 16 + ((lane >> 4) << 3)) * 2);
                ldsm4t(vh4, sVH + voff);
                ldsm4t(vl4, sVL + voff);
                mma16816(acc[np * 2], aH, vh4);
                mma16816(acc[np * 2], aH, vl4);
                mma16816(acc[np * 2], aL, vh4);
                mma16816(acc[np * 2 + 1], aH, vh4 + 2);
                mma16816(acc[np * 2 + 1], aH, vl4 + 2);
                mma16816(acc[np * 2 + 1], aL, vh4 + 2);
            }
        }
        __syncthreads();

        if (c + 2 < 8) {
            const uint32_t nb = sb + ((c & 1) ? AKV1 : AKV0);
            cp_pair(nb - sb, nb - sb + ATB, khp, klp, (c + 2) * 64);
            CP_COMMIT();
            cp_pair(nb - sb + 2 * ATB, nb - sb + 3 * ATB, vhp, vlp, (c + 2) * 64);
            CP_COMMIT();
        }
    }

    float* cb = (float*)(sm + AKV0);
    if (wh == 1) {
#pragma unroll
        for (int nt = 0; nt < 10; nt++) {
            int cc = nt * 8 + q2;
            cb[(wm + r4) * 80 + cc]     = acc[nt][0];
            cb[(wm + r4) * 80 + cc + 1] = acc[nt][1];
            cb[(wm + r4 + 8) * 80 + cc]     = acc[nt][2];
            cb[(wm + r4 + 8) * 80 + cc + 1] = acc[nt][3];
        }
        if ((lane & 3) == 0) {
            plsum[wm + r4] = lsum0;
            plsum[wm + r4 + 8] = lsum1;
        }
    }
    __syncthreads();
    if (wh == 0) {
        float li0 = 1.f / (lsum0 + plsum[wm + r4]);
        float li1 = 1.f / (lsum1 + plsum[wm + r4 + 8]);
        int gr0 = q0 + wm + r4;
#pragma unroll
        for (int nt = 0; nt < 10; nt++) {
            int col = h * HD + nt * 8 + q2;
            float x0 = (acc[nt][0] + cb[(wm + r4) * 80 + nt * 8 + q2]) * li0;
            float y0 = (acc[nt][1] + cb[(wm + r4) * 80 + nt * 8 + q2 + 1]) * li0;
            float x1 = (acc[nt][2] + cb[(wm + r4 + 8) * 80 + nt * 8 + q2]) * li1;
            float y1 = (acc[nt][3] + cb[(wm + r4 + 8) * 80 + nt * 8 + q2 + 1]) * li1;
            size_t a0 = (size_t)gr0 * DIM + col;
            size_t a1 = a0 + (size_t)8 * DIM;
            uint32_t lo;
            uint32_t hi = pk2(x0, y0, lo);
            *(uint32_t*)(ch + a0) = hi;
            *(uint32_t*)(cl + a0) = lo;
            hi = pk2(x1, y1, lo);
            *(uint32_t*)(ch + a1) = hi;
            *(uint32_t*)(cl + a1) = lo;
        }
    }
}

// ---------------------------------------------------------------------------
extern "C" void kernel_launch(void* const* d_in, const int* in_sizes, int n_in,
                              void* d_out, int out_size)
{
    const float* hs   = (const float*)d_in[0];
    const float* cosb = (const float*)d_in[1];
    const float* sinb = (const float*)d_in[2];
    const float* wq   = (const float*)d_in[3];
    const float* bq   = (const float*)d_in[4];
    const float* wk   = (const float*)d_in[5];
    const float* bk   = (const float*)d_in[6];
    const float* wv   = (const float*)d_in[7];
    const float* bv   = (const float*)d_in[8];
    const float* wo   = (const float*)d_in[9];
    const float* bo   = (const float*)d_in[10];
    float* out = (float*)d_out;

    float *qp, *kp, *vp;
    cudaGetSymbolAddress((void**)&qp, g_q);
    cudaGetSymbolAddress((void**)&kp, g_k);
    cudaGetSymbolAddress((void**)&vp, g_v);
    __nv_bfloat16 *ah, *al, *wh, *wl, *ch, *cl;
    cudaGetSymbolAddress((void**)&ah, g_ah);
    cudaGetSymbolAddress((void**)&al, g_al);
    cudaGetSymbolAddress((void**)&wh, g_wh);
    cudaGetSymbolAddress((void**)&wl, g_wl);
    cudaGetSymbolAddress((void**)&ch, g_ch);
    cudaGetSymbolAddress((void**)&cl, g_cl);

    cudaFuncSetAttribute(gemm_hmma,
                         cudaFuncAttributeMaxDynamicSharedMemorySize, GEMM_SMEM);
    cudaFuncSetAttribute(attn_mma,
                         cudaFuncAttributeMaxDynamicSharedMemorySize, ATTN_SMEM);

    split_hs<<<(S * DIM / 4) / 256, 256>>>((const float4*)hs, (uint2*)ah, (uint2*)al,
                                           S * DIM / 4);
    split_w4<<<dim3((DIM * DIM / 4) / 256, 4), 256>>>(
        (const float4*)wq, (const float4*)wk, (const float4*)wv, (const float4*)wo,
        (uint2*)wh, (uint2*)wl);

    gemm_hmma<<<dim3(DIM / GBN, S / GBM, 3), 256, GEMM_SMEM>>>(
        ah, al, wh, wl, 0, bq, bk, bv, qp, kp, vp);

    pack_qkv<<<S, 256>>>(cosb, sinb);

    attn_mma<<<dim3(8, NH, NSEG), 256, ATTN_SMEM>>>(ch, cl);

    gemm_hmma<<<dim3(DIM / GBN, S / GBM, 1), 256, GEMM_SMEM>>>(
        ch, cl, wh, wl, 3, bo, bo, bo, out, out, out);
}

// round 11
// speedup vs baseline: 1.2320x; 1.2320x over previous
#include <cuda_runtime.h>
#include <cuda_bf16.h>
#include <cuda_fp16.h>
#include <cstdint>
#include <math.h>

#define S    3072
#define DIM  1280
#define NH   16
#define HD   80
#define SEG  512
#define NSEG 6

// ---------------- scratch (__device__ globals; no allocs allowed) ----------
__device__ float g_q[S * DIM];
__device__ float g_k[S * DIM];
__device__ float g_v[S * DIM];

__device__ __half g_ah[S * DIM];              // hidden hi (fp16)
__device__ __half g_al[S * DIM];              // hidden lo (fp16)
__device__ __half g_wh[4 * DIM * DIM];        // weights hi only (fp16)
__device__ __half g_ch[S * DIM];              // ctx hi
__device__ __half g_cl[S * DIM];              // ctx lo

// attention operands (bf16x3, unchanged)
__device__ __nv_bfloat16 g_qh[NH * S * HD];
__device__ __nv_bfloat16 g_ql[NH * S * HD];
__device__ __nv_bfloat16 g_kh[NH * S * HD];
__device__ __nv_bfloat16 g_kl[NH * S * HD];
__device__ __nv_bfloat16 g_vh[NH * S * HD];
__device__ __nv_bfloat16 g_vl[NH * S * HD];

// ---------------- PTX helpers (sm_80-era, arch-neutral) --------------------
__device__ __forceinline__ uint32_t smem_u32(const void* p) {
    uint32_t a;
    asm("{ .reg .u64 t; cvta.to.shared.u64 t, %1; cvt.u32.u64 %0, t; }"
        : "=r"(a) : "l"(p));
    return a;
}
__device__ __forceinline__ void ldsm4(uint32_t* r, uint32_t addr) {
    asm volatile("ldmatrix.sync.aligned.m8n8.x4.shared.b16 {%0,%1,%2,%3}, [%4];"
                 : "=r"(r[0]), "=r"(r[1]), "=r"(r[2]), "=r"(r[3]) : "r"(addr));
}
__device__ __forceinline__ void ldsm4t(uint32_t* r, uint32_t addr) {
    asm volatile("ldmatrix.sync.aligned.m8n8.x4.trans.shared.b16 {%0,%1,%2,%3}, [%4];"
                 : "=r"(r[0]), "=r"(r[1]), "=r"(r[2]), "=r"(r[3]) : "r"(addr));
}
// bf16 MMA (attention)
__device__ __forceinline__ void mma16816(float* d, const uint32_t* a, const uint32_t* b) {
    asm volatile(
        "mma.sync.aligned.m16n8k16.row.col.f32.bf16.bf16.f32 "
        "{%0,%1,%2,%3}, {%4,%5,%6,%7}, {%8,%9}, {%0,%1,%2,%3};"
        : "+f"(d[0]), "+f"(d[1]), "+f"(d[2]), "+f"(d[3])
        : "r"(a[0]), "r"(a[1]), "r"(a[2]), "r"(a[3]), "r"(b[0]), "r"(b[1]));
}
// fp16 MMA (projections)
__device__ __forceinline__ void mma16816h(float* d, const uint32_t* a, const uint32_t* b) {
    asm volatile(
        "mma.sync.aligned.m16n8k16.row.col.f32.f16.f16.f32 "
        "{%0,%1,%2,%3}, {%4,%5,%6,%7}, {%8,%9}, {%0,%1,%2,%3};"
        : "+f"(d[0]), "+f"(d[1]), "+f"(d[2]), "+f"(d[3])
        : "r"(a[0]), "r"(a[1]), "r"(a[2]), "r"(a[3]), "r"(b[0]), "r"(b[1]));
}

#define CP_ASYNC16(dst, src) \
    asm volatile("cp.async.cg.shared.global [%0], [%1], 16;" :: "r"(dst), "l"(src))
#define CP_COMMIT() asm volatile("cp.async.commit_group;")
#define CP_WAIT3()  asm volatile("cp.async.wait_group 3;")
#define CP_WAIT2()  asm volatile("cp.async.wait_group 2;")
#define CP_WAIT1()  asm volatile("cp.async.wait_group 1;")
#define CP_WAIT0()  asm volatile("cp.async.wait_group 0;")

// bf16 hi/lo pack (attention path)
__device__ __forceinline__ uint32_t pk2(float x, float y, uint32_t& lo) {
    __nv_bfloat162 h, l;
    h.x = __float2bfloat16(x); h.y = __float2bfloat16(y);
    l.x = __float2bfloat16(x - __bfloat162float(h.x));
    l.y = __float2bfloat16(y - __bfloat162float(h.y));
    lo = *(uint32_t*)&l;
    return *(uint32_t*)&h;
}
// fp16 hi/lo pack (gemm path)
__device__ __forceinline__ uint32_t pk2h(float x, float y, uint32_t& lo) {
    __half hx = __float2half_rn(x), hy = __float2half_rn(y);
    __half lx = __float2half_rn(x - __half2float(hx));
    __half ly = __float2half_rn(y - __half2float(hy));
    __half2 H = __halves2half2(hx, hy), L = __halves2half2(lx, ly);
    lo = *(uint32_t*)&L;
    return *(uint32_t*)&H;
}
__device__ __forceinline__ uint32_t pkh(float x, float y) {
    __half2 H = __halves2half2(__float2half_rn(x), __float2half_rn(y));
    return *(uint32_t*)&H;
}

// ---------------- fp32 -> fp16 hi/lo splits ---------------------------------
__global__ void split_hs(const float4* __restrict__ src,
                         uint2* __restrict__ hi, uint2* __restrict__ lo, int n4) {
    int i = blockIdx.x * blockDim.x + threadIdx.x;
    if (i < n4) {
        float4 v = src[i];
        uint32_t l0, l1;
        uint32_t h0 = pk2h(v.x, v.y, l0);
        uint32_t h1 = pk2h(v.z, v.w, l1);
        hi[i] = make_uint2(h0, h1);
        lo[i] = make_uint2(l0, l1);
    }
}

// weights: hi only
__global__ void split_w4(const float4* __restrict__ s0, const float4* __restrict__ s1,
                         const float4* __restrict__ s2, const float4* __restrict__ s3,
                         uint2* __restrict__ hi) {
    int z = blockIdx.y;
    const float4* s = (z == 0) ? s0 : (z == 1) ? s1 : (z == 2) ? s2 : s3;
    size_t base = (size_t)z * (DIM * DIM / 4);
    int i = blockIdx.x * blockDim.x + threadIdx.x;
    float4 v = s[i];
    hi[base + i] = make_uint2(pkh(v.x, v.y), pkh(v.z, v.w));
}

// ---------------- HMMA fp16x2 GEMM ------------------------------------------
// C = Ah@Wh^T + Al@Wh^T + bias.  A fp16 hi/lo, W fp16 hi only.
#define GBM 128
#define GBN 128
#define NCHUNK (DIM / 32)
#define TSTRIDE 80
#define TILE_B  (128 * TSTRIDE)      // 10240
#define STAGE_B (3 * TILE_B)         // 30720 (Ah, Al, Wh)
#define GEMM_SMEM (2 * STAGE_B)      // 61440

__global__ __launch_bounds__(256, 2) void gemm_hmma(
    const __half* __restrict__ Ahi, const __half* __restrict__ Alo,
    const __half* __restrict__ Wh_base,
    int zoff,
    const float* __restrict__ bias0, const float* __restrict__ bias1, const float* __restrict__ bias2,
    float* __restrict__ C0, float* __restrict__ C1, float* __restrict__ C2)
{
    extern __shared__ char smem[];
    const uint32_t sb = smem_u32(smem);
    const int tid  = threadIdx.x;
    const int wid  = tid >> 5;
    const int lane = tid & 31;

    const int z = blockIdx.z;
    const __half* Wh = Wh_base + (size_t)(zoff + z) * DIM * DIM;
    const float* bias = (z == 0) ? bias0 : (z == 1) ? bias1 : bias2;
    float* C = (z == 0) ? C0 : (z == 1) ? C1 : C2;

    const int m0 = blockIdx.y * GBM;
    const int n0 = blockIdx.x * GBN;
    const int wm = (wid & 1) * 64;
    const int wn = (wid >> 1) * 32;

    const char* srcs[3];
    srcs[0] = (const char*)(Ahi + (size_t)m0 * DIM);
    srcs[1] = (const char*)(Alo + (size_t)m0 * DIM);
    srcs[2] = (const char*)(Wh  + (size_t)n0 * DIM);

    float acc[4][4][4];
#pragma unroll
    for (int mt = 0; mt < 4; mt++)
#pragma unroll
        for (int nt = 0; nt < 4; nt++)
#pragma unroll
            for (int i = 0; i < 4; i++) acc[mt][nt][i] = 0.f;

    // load chunk 0 into buffer 0
    {
#pragma unroll
        for (int i = 0; i < 6; i++) {
            int t = i >> 1;
            int e = (i & 1) * 256 + tid;     // 0..511
            int row = e >> 2, c16 = e & 3;
            CP_ASYNC16(sb + t * TILE_B + row * TSTRIDE + c16 * 16,
                       srcs[t] + (size_t)row * (DIM * 2) + c16 * 16);
        }
        CP_COMMIT();
    }

    const int arow = lane & 15;
    const int acolh = (lane >> 4) * 16;
    const int browa = ((lane >> 4) << 3) + (lane & 7);
    const int bcolh = ((lane >> 3) & 1) * 16;

    for (int c = 0; c < NCHUNK; c++) {
        if (c + 1 < NCHUNK) {
            const int k0b = (c + 1) * 64;    // bytes into row
            uint32_t d = sb + ((c + 1) & 1) * STAGE_B;
#pragma unroll
            for (int i = 0; i < 6; i++) {
                int t = i >> 1;
                int e = (i & 1) * 256 + tid;
                int row = e >> 2, c16 = e & 3;
                CP_ASYNC16(d + t * TILE_B + row * TSTRIDE + c16 * 16,
                           srcs[t] + (size_t)row * (DIM * 2) + k0b + c16 * 16);
            }
            CP_COMMIT();
            CP_WAIT1();
        } else {
            CP_WAIT0();
        }
        __syncthreads();

        const uint32_t stage = sb + (c & 1) * STAGE_B;
        const uint32_t sAh = stage;
        const uint32_t sAl = stage + TILE_B;
        const uint32_t sWh = stage + 2 * TILE_B;

#pragma unroll
        for (int ks = 0; ks < 2; ks++) {
            const int acol = ks * 32 + acolh;
            uint32_t bh[8];
            {
                uint32_t boff = (uint32_t)((wn + browa) * TSTRIDE + ks * 32 + bcolh);
                ldsm4(bh,     sWh + boff);
                ldsm4(bh + 4, sWh + boff + 16 * TSTRIDE);
            }
#pragma unroll
            for (int mt = 0; mt < 4; mt++) {
                uint32_t ah[4], al[4];
                uint32_t off = (uint32_t)((wm + mt * 16 + arow) * TSTRIDE + acol);
                ldsm4(ah, sAh + off);
                ldsm4(al, sAl + off);
#pragma unroll
                for (int nt = 0; nt < 4; nt++) {
                    mma16816h(acc[mt][nt], ah, bh + nt * 2);
                    mma16816h(acc[mt][nt], al, bh + nt * 2);
                }
            }
        }
        __syncthreads();
    }

    const int r0 = lane >> 2;
    const int c0 = (lane & 3) * 2;
#pragma unroll
    for (int mt = 0; mt < 4; mt++) {
#pragma unroll
        for (int nt = 0; nt < 4; nt++) {
            int gm = m0 + wm + mt * 16 + r0;
            int gn = n0 + wn + nt * 8 + c0;
            float2 bv = *(const float2*)(bias + gn);
            float2 o0, o1;
            o0.x = acc[mt][nt][0] + bv.x;
            o0.y = acc[mt][nt][1] + bv.y;
            o1.x = acc[mt][nt][2] + bv.x;
            o1.y = acc[mt][nt][3] + bv.y;
            *(float2*)(C + (size_t)gm * DIM + gn) = o0;
            *(float2*)(C + (size_t)(gm + 8) * DIM + gn) = o1;
        }
    }
}

// ---------------- pack: rope + scale + split + per-head relayout (bf16) -----
__global__ void pack_qkv(const float* __restrict__ cosb,
                         const float* __restrict__ sinb)
{
    const int s = blockIdx.x;
    const int tid = threadIdx.x;
    const float scale = 0.11180339887498949f;

    for (int p = tid; p < NH * 20; p += 256) {
        int h = p / 20, dp = (p % 20) * 2;
        float2 c2 = *(const float2*)(cosb + s * HD + dp);
        float2 s2 = *(const float2*)(sinb + s * HD + dp);
        size_t ib = (size_t)s * DIM + h * HD + dp;
        size_t ob = ((size_t)h * S + s) * HD + dp;

        float2 qa = *(const float2*)(g_q + ib);
        float2 qb = *(const float2*)(g_q + ib + 40);
        float q1x = (qa.x * c2.x - qb.x * s2.x) * scale;
        float q1y = (qa.y * c2.y - qb.y * s2.y) * scale;
        float q2x = (qb.x * c2.x + qa.x * s2.x) * scale;
        float q2y = (qb.y * c2.y + qa.y * s2.y) * scale;
        uint32_t lo, hi;
        hi = pk2(q1x, q1y, lo);
        *(uint32_t*)(g_qh + ob) = hi;      *(uint32_t*)(g_ql + ob) = lo;
        hi = pk2(q2x, q2y, lo);
        *(uint32_t*)(g_qh + ob + 40) = hi; *(uint32_t*)(g_ql + ob + 40) = lo;

        float2 ka = *(const float2*)(g_k + ib);
        float2 kb = *(const float2*)(g_k + ib + 40);
        float k1x = ka.x * c2.x - kb.x * s2.x;
        float k1y = ka.y * c2.y - kb.y * s2.y;
        float k2x = kb.x * c2.x + ka.x * s2.x;
        float k2y = kb.y * c2.y + ka.y * s2.y;
        hi = pk2(k1x, k1y, lo);
        *(uint32_t*)(g_kh + ob) = hi;      *(uint32_t*)(g_kl + ob) = lo;
        hi = pk2(k2x, k2y, lo);
        *(uint32_t*)(g_kh + ob + 40) = hi; *(uint32_t*)(g_kl + ob + 40) = lo;
    }

    for (int p = tid; p < DIM / 2; p += 256) {
        int e = p * 2;
        int h = e / HD, d = e % HD;
        float2 v2 = *(const float2*)(g_v + (size_t)s * DIM + e);
        size_t ob = ((size_t)h * S + s) * HD + d;
        uint32_t lo, hi;
        hi = pk2(v2.x, v2.y, lo);
        *(uint32_t*)(g_vh + ob) = hi;
        *(uint32_t*)(g_vl + ob) = lo;
    }
}

// ---------------- flash attention: register S/P, double-buffered KV ---------
#define ATS 176
#define ATB (64 * ATS)
#define AQH 0
#define AQL ATB
#define AKV0 (2 * ATB)
#define AKV1 (6 * ATB)
#define APMAX (10 * ATB)
#define APLS  (APMAX + 512)
#define ATTN_SMEM (APLS + 256)        // 113408 B

__global__ __launch_bounds__(256, 2) void attn_mma(__half* __restrict__ ch,
                                                   __half* __restrict__ cl)
{
    extern __shared__ char sm[];
    const uint32_t sb = smem_u32(sm);
    const int tid = threadIdx.x;
    const int wid = tid >> 5;
    const int lane = tid & 31;

    const int qt = blockIdx.x;
    const int h  = blockIdx.y;
    const int sg = blockIdx.z;
    const int s0 = sg * SEG;
    const int q0 = s0 + qt * 64;
    const size_t hb = (size_t)h * S * HD;

    const int wm = (wid & 3) * 16;
    const int wh = wid >> 2;
    const int wn = wh * 32;

    float* pmax = (float*)(sm + APMAX);
    float* plsum = (float*)(sm + APLS);

    const char* qhp = (const char*)(g_qh + hb + (size_t)q0 * HD);
    const char* qlp = (const char*)(g_ql + hb + (size_t)q0 * HD);
    const char* khp = (const char*)(g_kh + hb + (size_t)s0 * HD);
    const char* klp = (const char*)(g_kl + hb + (size_t)s0 * HD);
    const char* vhp = (const char*)(g_vh + hb + (size_t)s0 * HD);
    const char* vlp = (const char*)(g_vl + hb + (size_t)s0 * HD);

    auto cp_pair = [&](uint32_t dH, uint32_t dL, const char* srcH, const char* srcL, int rb) {
#pragma unroll
        for (int i = 0; i < 5; i++) {
            int f = i * 256 + tid;
            int sel = f >= 640;
            int g = f - (sel ? 640 : 0);
            int r = g / 10, c = g - r * 10;
            CP_ASYNC16(sb + (sel ? dL : dH) + r * ATS + c * 16,
                       (sel ? srcL : srcH) + (size_t)(rb + r) * 160 + c * 16);
        }
    };

    cp_pair(AQH, AQL, qhp, qlp, 0);
    cp_pair(AKV0, AKV0 + ATB, khp, klp, 0);
    CP_COMMIT();
    cp_pair(AKV0 + 2 * ATB, AKV0 + 3 * ATB, vhp, vlp, 0);
    CP_COMMIT();
    cp_pair(AKV1, AKV1 + ATB, khp, klp, 64);
    CP_COMMIT();
    cp_pair(AKV1 + 2 * ATB, AKV1 + 3 * ATB, vhp, vlp, 64);
    CP_COMMIT();

    float acc[10][4];
#pragma unroll
    for (int nt = 0; nt < 10; nt++)
#pragma unroll
        for (int i = 0; i < 4; i++) acc[nt][i] = 0.f;

    float mold0 = -1e30f, mold1 = -1e30f;
    float lsum0 = 0.f, lsum1 = 0.f;

    const int qrow = wm + (lane & 15);
    const uint32_t qcoloff = (uint32_t)((lane >> 4) * 16);
    const int krowa = wn + ((lane >> 4) << 3) + (lane & 7);
    const uint32_t kcoloff = (uint32_t)(((lane >> 3) & 1) * 16);
    const int r4 = lane >> 2;
    const int q2 = (lane & 3) * 2;

    for (int c = 0; c < 8; c++) {
        const uint32_t kv = sb + ((c & 1) ? AKV1 : AKV0);
        const uint32_t sKH = kv, sKL = kv + ATB, sVH = kv + 2 * ATB, sVL = kv + 3 * ATB;

        if (c == 7) { CP_WAIT1(); } else { CP_WAIT3(); }
        __syncthreads();

        float sa[4][4];
#pragma unroll
        for (int nt = 0; nt < 4; nt++)
#pragma unroll
            for (int i = 0; i < 4; i++) sa[nt][i] = 0.f;

#pragma unroll
        for (int ks = 0; ks < 5; ks++) {
            uint32_t qh4[4], ql4[4], kh[8], kl[8];
            uint32_t qoff = (uint32_t)(qrow * ATS + ks * 32) + qcoloff;
            ldsm4(qh4, sb + AQH + qoff);
            ldsm4(ql4, sb + AQL + qoff);
            uint32_t koff0 = (uint32_t)(krowa * ATS + ks * 32) + kcoloff;
            ldsm4(kh,     sKH + koff0);
            ldsm4(kh + 4, sKH + koff0 + 16 * ATS);
            ldsm4(kl,     sKL + koff0);
            ldsm4(kl + 4, sKL + koff0 + 16 * ATS);
#pragma unroll
            for (int nt = 0; nt < 4; nt++) {
                mma16816(sa[nt], qh4, kh + nt * 2);
                mma16816(sa[nt], qh4, kl + nt * 2);
                mma16816(sa[nt], ql4, kh + nt * 2);
            }
        }

        float mx0 = fmaxf(fmaxf(sa[0][0], sa[0][1]), fmaxf(sa[1][0], sa[1][1]));
        mx0 = fmaxf(mx0, fmaxf(fmaxf(sa[2][0], sa[2][1]), fmaxf(sa[3][0], sa[3][1])));
        float mx1 = fmaxf(fmaxf(sa[0][2], sa[0][3]), fmaxf(sa[1][2], sa[1][3]));
        mx1 = fmaxf(mx1, fmaxf(fmaxf(sa[2][2], sa[2][3]), fmaxf(sa[3][2], sa[3][3])));
        mx0 = fmaxf(mx0, __shfl_xor_sync(0xffffffffu, mx0, 1));
        mx0 = fmaxf(mx0, __shfl_xor_sync(0xffffffffu, mx0, 2));
        mx1 = fmaxf(mx1, __shfl_xor_sync(0xffffffffu, mx1, 1));
        mx1 = fmaxf(mx1, __shfl_xor_sync(0xffffffffu, mx1, 2));
        if ((lane & 3) == 0) {
            pmax[wh * 64 + wm + r4] = mx0;
            pmax[wh * 64 + wm + 8 + r4] = mx1;
        }

        if (c == 7) { CP_WAIT0(); } else { CP_WAIT2(); }
        __syncthreads();

        float ma0 = fmaxf(pmax[wm + r4], pmax[64 + wm + r4]);
        float ma1 = fmaxf(pmax[wm + 8 + r4], pmax[64 + wm + 8 + r4]);
        float mn0 = fmaxf(mold0, ma0);
        float mn1 = fmaxf(mold1, ma1);
        float fs0 = __expf(mold0 - mn0);
        float fs1 = __expf(mold1 - mn1);
        mold0 = mn0; mold1 = mn1;

        float s0r = 0.f, s1r = 0.f;
#pragma unroll
        for (int nt = 0; nt < 4; nt++) {
            sa[nt][0] = __expf(sa[nt][0] - mn0);
            sa[nt][1] = __expf(sa[nt][1] - mn0);
            sa[nt][2] = __expf(sa[nt][2] - mn1);
            sa[nt][3] = __expf(sa[nt][3] - mn1);
            s0r += sa[nt][0] + sa[nt][1];
            s1r += sa[nt][2] + sa[nt][3];
        }
        s0r += __shfl_xor_sync(0xffffffffu, s0r, 1);
        s0r += __shfl_xor_sync(0xffffffffu, s0r, 2);
        s1r += __shfl_xor_sync(0xffffffffu, s1r, 1);
        s1r += __shfl_xor_sync(0xffffffffu, s1r, 2);
        lsum0 = lsum0 * fs0 + s0r;
        lsum1 = lsum1 * fs1 + s1r;

#pragma unroll
        for (int nt = 0; nt < 10; nt++) {
            acc[nt][0] *= fs0; acc[nt][1] *= fs0;
            acc[nt][2] *= fs1; acc[nt][3] *= fs1;
        }

#pragma unroll
        for (int kb = 0; kb < 2; kb++) {
            uint32_t aH[4], aL[4];
            aH[0] = pk2(sa[2 * kb][0], sa[2 * kb][1], aL[0]);
            aH[1] = pk2(sa[2 * kb][2], sa[2 * kb][3], aL[1]);
            aH[2] = pk2(sa[2 * kb + 1][0], sa[2 * kb + 1][1], aL[2]);
            aH[3] = pk2(sa[2 * kb + 1][2], sa[2 * kb + 1][3], aL[3]);
            const int vrow = wn + kb * 16 + (lane & 15);
#pragma unroll
            for (int np = 0; np < 5; np++) {
                uint32_t vh4[4], vl4[4];
                uint32_t voff = (uint32_t)(vrow * ATS + (np * 16 + ((lane >> 4) << 3)) * 2);
                ldsm4t(vh4, sVH + voff);
                ldsm4t(vl4, sVL + voff);
                mma16816(acc[np * 2], aH, vh4);
                mma16816(acc[np * 2], aH, vl4);
                mma16816(acc[np * 2], aL, vh4);
                mma16816(acc[np * 2 + 1], aH, vh4 + 2);
                mma16816(acc[np * 2 + 1], aH, vl4 + 2);
                mma16816(acc[np * 2 + 1], aL, vh4 + 2);
            }
        }
        __syncthreads();

        if (c + 2 < 8) {
            const uint32_t nb = sb + ((c & 1) ? AKV1 : AKV0);
            cp_pair(nb - sb, nb - sb + ATB, khp, klp, (c + 2) * 64);
            CP_COMMIT();
            cp_pair(nb - sb + 2 * ATB, nb - sb + 3 * ATB, vhp, vlp, (c + 2) * 64);
            CP_COMMIT();
        }
    }

    float* cb = (float*)(sm + AKV0);
    if (wh == 1) {
#pragma unroll
        for (int nt = 0; nt < 10; nt++) {
            int cc = nt * 8 + q2;
            cb[(wm + r4) * 80 + cc]     = acc[nt][0];
            cb[(wm + r4) * 80 + cc + 1] = acc[nt][1];
            cb[(wm + r4 + 8) * 80 + cc]     = acc[nt][2];
            cb[(wm + r4 + 8) * 80 + cc + 1] = acc[nt][3];
        }
        if ((lane & 3) == 0) {
            plsum[wm + r4] = lsum0;
            plsum[wm + r4 + 8] = lsum1;
        }
    }
    __syncthreads();
    if (wh == 0) {
        float li0 = 1.f / (lsum0 + plsum[wm + r4]);
        float li1 = 1.f / (lsum1 + plsum[wm + r4 + 8]);
        int gr0 = q0 + wm + r4;
#pragma unroll
        for (int nt = 0; nt < 10; nt++) {
            int col = h * HD + nt * 8 + q2;
            float x0 = (acc[nt][0] + cb[(wm + r4) * 80 + nt * 8 + q2]) * li0;
            float y0 = (acc[nt][1] + cb[(wm + r4) * 80 + nt * 8 + q2 + 1]) * li0;
            float x1 = (acc[nt][2] + cb[(wm + r4 + 8) * 80 + nt * 8 + q2]) * li1;
            float y1 = (acc[nt][3] + cb[(wm + r4 + 8) * 80 + nt * 8 + q2 + 1]) * li1;
            size_t a0 = (size_t)gr0 * DIM + col;
            size_t a1 = a0 + (size_t)8 * DIM;
            uint32_t lo;
            uint32_t hi = pk2h(x0, y0, lo);
            *(uint32_t*)(ch + a0) = hi;
            *(uint32_t*)(cl + a0) = lo;
            hi = pk2h(x1, y1, lo);
            *(uint32_t*)(ch + a1) = hi;
            *(uint32_t*)(cl + a1) = lo;
        }
    }
}

// ---------------------------------------------------------------------------
extern "C" void kernel_launch(void* const* d_in, const int* in_sizes, int n_in,
                              void* d_out, int out_size)
{
    const float* hs   = (const float*)d_in[0];
    const float* cosb = (const float*)d_in[1];
    const float* sinb = (const float*)d_in[2];
    const float* wq   = (const float*)d_in[3];
    const float* bq   = (const float*)d_in[4];
    const float* wk   = (const float*)d_in[5];
    const float* bk   = (const float*)d_in[6];
    const float* wv   = (const float*)d_in[7];
    const float* bv   = (const float*)d_in[8];
    const float* wo   = (const float*)d_in[9];
    const float* bo   = (const float*)d_in[10];
    float* out = (float*)d_out;

    float *qp, *kp, *vp;
    cudaGetSymbolAddress((void**)&qp, g_q);
    cudaGetSymbolAddress((void**)&kp, g_k);
    cudaGetSymbolAddress((void**)&vp, g_v);
    __half *ah, *al, *wh, *ch, *cl;
    cudaGetSymbolAddress((void**)&ah, g_ah);
    cudaGetSymbolAddress((void**)&al, g_al);
    cudaGetSymbolAddress((void**)&wh, g_wh);
    cudaGetSymbolAddress((void**)&ch, g_ch);
    cudaGetSymbolAddress((void**)&cl, g_cl);

    cudaFuncSetAttribute(gemm_hmma,
                         cudaFuncAttributeMaxDynamicSharedMemorySize, GEMM_SMEM);
    cudaFuncSetAttribute(attn_mma,
                         cudaFuncAttributeMaxDynamicSharedMemorySize, ATTN_SMEM);

    split_hs<<<(S * DIM / 4) / 256, 256>>>((const float4*)hs, (uint2*)ah, (uint2*)al,
                                           S * DIM / 4);
    split_w4<<<dim3((DIM * DIM / 4) / 256, 4), 256>>>(
        (const float4*)wq, (const float4*)wk, (const float4*)wv, (const float4*)wo,
        (uint2*)wh);

    gemm_hmma<<<dim3(DIM / GBN, S / GBM, 3), 256, GEMM_SMEM>>>(
        ah, al, wh, 0, bq, bk, bv, qp, kp, vp);

    pack_qkv<<<S, 256>>>(cosb, sinb);

    attn_mma<<<dim3(8, NH, NSEG), 256, ATTN_SMEM>>>(ch, cl);

    gemm_hmma<<<dim3(DIM / GBN, S / GBM, 1), 256, GEMM_SMEM>>>(
        ch, cl, wh, 3, bo, bo, bo, out, out, out);
}

// round 12
// speedup vs baseline: 1.3315x; 1.0808x over previous
#include <cuda_runtime.h>
#include <cuda_bf16.h>
#include <cuda_fp16.h>
#include <cstdint>
#include <math.h>

#define S    3072
#define DIM  1280
#define NH   16
#define HD   80
#define SEG  512
#define NSEG 6

// ---------------- scratch (__device__ globals; no allocs allowed) ----------
__device__ float g_q[S * DIM];
__device__ float g_k[S * DIM];
__device__ float g_v[S * DIM];

__device__ __half g_ah[S * DIM];              // hidden hi (fp16)
__device__ __half g_al[S * DIM];              // hidden lo (fp16)
__device__ __half g_wh[4 * DIM * DIM];        // weights hi only (fp16)
__device__ __half g_ch[S * DIM];              // ctx hi
__device__ __half g_cl[S * DIM];              // ctx lo

// attention operands (bf16x3, unchanged)
__device__ __nv_bfloat16 g_qh[NH * S * HD];
__device__ __nv_bfloat16 g_ql[NH * S * HD];
__device__ __nv_bfloat16 g_kh[NH * S * HD];
__device__ __nv_bfloat16 g_kl[NH * S * HD];
__device__ __nv_bfloat16 g_vh[NH * S * HD];
__device__ __nv_bfloat16 g_vl[NH * S * HD];

// ---------------- PTX helpers (sm_80-era, arch-neutral) --------------------
__device__ __forceinline__ uint32_t smem_u32(const void* p) {
    uint32_t a;
    asm("{ .reg .u64 t; cvta.to.shared.u64 t, %1; cvt.u32.u64 %0, t; }"
        : "=r"(a) : "l"(p));
    return a;
}
__device__ __forceinline__ void ldsm4(uint32_t* r, uint32_t addr) {
    asm volatile("ldmatrix.sync.aligned.m8n8.x4.shared.b16 {%0,%1,%2,%3}, [%4];"
                 : "=r"(r[0]), "=r"(r[1]), "=r"(r[2]), "=r"(r[3]) : "r"(addr));
}
__device__ __forceinline__ void ldsm4t(uint32_t* r, uint32_t addr) {
    asm volatile("ldmatrix.sync.aligned.m8n8.x4.trans.shared.b16 {%0,%1,%2,%3}, [%4];"
                 : "=r"(r[0]), "=r"(r[1]), "=r"(r[2]), "=r"(r[3]) : "r"(addr));
}
// bf16 MMA (attention)
__device__ __forceinline__ void mma16816(float* d, const uint32_t* a, const uint32_t* b) {
    asm volatile(
        "mma.sync.aligned.m16n8k16.row.col.f32.bf16.bf16.f32 "
        "{%0,%1,%2,%3}, {%4,%5,%6,%7}, {%8,%9}, {%0,%1,%2,%3};"
        : "+f"(d[0]), "+f"(d[1]), "+f"(d[2]), "+f"(d[3])
        : "r"(a[0]), "r"(a[1]), "r"(a[2]), "r"(a[3]), "r"(b[0]), "r"(b[1]));
}
// fp16 MMA (projections)
__device__ __forceinline__ void mma16816h(float* d, const uint32_t* a, const uint32_t* b) {
    asm volatile(
        "mma.sync.aligned.m16n8k16.row.col.f32.f16.f16.f32 "
        "{%0,%1,%2,%3}, {%4,%5,%6,%7}, {%8,%9}, {%0,%1,%2,%3};"
        : "+f"(d[0]), "+f"(d[1]), "+f"(d[2]), "+f"(d[3])
        : "r"(a[0]), "r"(a[1]), "r"(a[2]), "r"(a[3]), "r"(b[0]), "r"(b[1]));
}

#define CP_ASYNC16(dst, src) \
    asm volatile("cp.async.cg.shared.global [%0], [%1], 16;" :: "r"(dst), "l"(src))
#define CP_COMMIT() asm volatile("cp.async.commit_group;")
#define CP_WAIT3()  asm volatile("cp.async.wait_group 3;")
#define CP_WAIT2()  asm volatile("cp.async.wait_group 2;")
#define CP_WAIT1()  asm volatile("cp.async.wait_group 1;")
#define CP_WAIT0()  asm volatile("cp.async.wait_group 0;")

// bf16 hi/lo pack (attention path)
__device__ __forceinline__ uint32_t pk2(float x, float y, uint32_t& lo) {
    __nv_bfloat162 h, l;
    h.x = __float2bfloat16(x); h.y = __float2bfloat16(y);
    l.x = __float2bfloat16(x - __bfloat162float(h.x));
    l.y = __float2bfloat16(y - __bfloat162float(h.y));
    lo = *(uint32_t*)&l;
    return *(uint32_t*)&h;
}
// fp16 hi/lo pack (gemm path)
__device__ __forceinline__ uint32_t pk2h(float x, float y, uint32_t& lo) {
    __half hx = __float2half_rn(x), hy = __float2half_rn(y);
    __half lx = __float2half_rn(x - __half2float(hx));
    __half ly = __float2half_rn(y - __half2float(hy));
    __half2 H = __halves2half2(hx, hy), L = __halves2half2(lx, ly);
    lo = *(uint32_t*)&L;
    return *(uint32_t*)&H;
}
__device__ __forceinline__ uint32_t pkh(float x, float y) {
    __half2 H = __halves2half2(__float2half_rn(x), __float2half_rn(y));
    return *(uint32_t*)&H;
}

// ---------------- fp32 -> fp16 hi/lo splits ---------------------------------
__global__ void split_hs(const float4* __restrict__ src,
                         uint2* __restrict__ hi, uint2* __restrict__ lo, int n4) {
    int i = blockIdx.x * blockDim.x + threadIdx.x;
    if (i < n4) {
        float4 v = src[i];
        uint32_t l0, l1;
        uint32_t h0 = pk2h(v.x, v.y, l0);
        uint32_t h1 = pk2h(v.z, v.w, l1);
        hi[i] = make_uint2(h0, h1);
        lo[i] = make_uint2(l0, l1);
    }
}

__global__ void split_w4(const float4* __restrict__ s0, const float4* __restrict__ s1,
                         const float4* __restrict__ s2, const float4* __restrict__ s3,
                         uint2* __restrict__ hi) {
    int z = blockIdx.y;
    const float4* s = (z == 0) ? s0 : (z == 1) ? s1 : (z == 2) ? s2 : s3;
    size_t base = (size_t)z * (DIM * DIM / 4);
    int i = blockIdx.x * blockDim.x + threadIdx.x;
    float4 v = s[i];
    hi[base + i] = make_uint2(pkh(v.x, v.y), pkh(v.z, v.w));
}

// ---------------- HMMA fp16x2 GEMM, BK=64 -----------------------------------
// C = Ah@Wh^T + Al@Wh^T + bias.  K chunks of 64 fp16 (128B rows), 20 chunks.
#define GBM 128
#define GBN 128
#define NCHUNK (DIM / 64)            // 20
#define TSTRIDE 144                  // 128B row + 16B pad (odd multiple of 16)
#define TILE_B  (128 * TSTRIDE)      // 18432
#define STAGE_B (3 * TILE_B)         // 55296 (Ah, Al, Wh)
#define GEMM_SMEM (2 * STAGE_B)      // 110592

__global__ __launch_bounds__(256, 2) void gemm_hmma(
    const __half* __restrict__ Ahi, const __half* __restrict__ Alo,
    const __half* __restrict__ Wh_base,
    int zoff,
    const float* __restrict__ bias0, const float* __restrict__ bias1, const float* __restrict__ bias2,
    float* __restrict__ C0, float* __restrict__ C1, float* __restrict__ C2)
{
    extern __shared__ char smem[];
    const uint32_t sb = smem_u32(smem);
    const int tid  = threadIdx.x;
    const int wid  = tid >> 5;
    const int lane = tid & 31;

    const int z = blockIdx.z;
    const __half* Wh = Wh_base + (size_t)(zoff + z) * DIM * DIM;
    const float* bias = (z == 0) ? bias0 : (z == 1) ? bias1 : bias2;
    float* C = (z == 0) ? C0 : (z == 1) ? C1 : C2;

    const int m0 = blockIdx.y * GBM;
    const int n0 = blockIdx.x * GBN;
    const int wm = (wid & 1) * 64;
    const int wn = (wid >> 1) * 32;

    const char* srcs[3];
    srcs[0] = (const char*)(Ahi + (size_t)m0 * DIM);
    srcs[1] = (const char*)(Alo + (size_t)m0 * DIM);
    srcs[2] = (const char*)(Wh  + (size_t)n0 * DIM);

    float acc[4][4][4];
#pragma unroll
    for (int mt = 0; mt < 4; mt++)
#pragma unroll
        for (int nt = 0; nt < 4; nt++)
#pragma unroll
            for (int i = 0; i < 4; i++) acc[mt][nt][i] = 0.f;

    // load chunk 0 into buffer 0 (3 tiles x 128 rows x 128B = 12 cp16/thread)
    {
#pragma unroll
        for (int i = 0; i < 12; i++) {
            int t = i >> 2;
            int e = (i & 3) * 256 + tid;     // 0..1023
            int row = e >> 3, c16 = e & 7;
            CP_ASYNC16(sb + t * TILE_B + row * TSTRIDE + c16 * 16,
                       srcs[t] + (size_t)row * (DIM * 2) + c16 * 16);
        }
        CP_COMMIT();
    }

    const int arow = lane & 15;
    const int acolh = (lane >> 4) * 16;
    const int browa = ((lane >> 4) << 3) + (lane & 7);
    const int bcolh = ((lane >> 3) & 1) * 16;

    for (int c = 0; c < NCHUNK; c++) {
        if (c + 1 < NCHUNK) {
            const int k0b = (c + 1) * 128;   // bytes into row
            uint32_t d = sb + ((c + 1) & 1) * STAGE_B;
#pragma unroll
            for (int i = 0; i < 12; i++) {
                int t = i >> 2;
                int e = (i & 3) * 256 + tid;
                int row = e >> 3, c16 = e & 7;
                CP_ASYNC16(d + t * TILE_B + row * TSTRIDE + c16 * 16,
                           srcs[t] + (size_t)row * (DIM * 2) + k0b + c16 * 16);
            }
            CP_COMMIT();
            CP_WAIT1();
        } else {
            CP_WAIT0();
        }
        __syncthreads();

        const uint32_t stage = sb + (c & 1) * STAGE_B;
        const uint32_t sAh = stage;
        const uint32_t sAl = stage + TILE_B;
        const uint32_t sWh = stage + 2 * TILE_B;

#pragma unroll
        for (int ks = 0; ks < 4; ks++) {
            const int acol = ks * 32 + acolh;
            uint32_t bh[8];
            {
                uint32_t boff = (uint32_t)((wn + browa) * TSTRIDE + ks * 32 + bcolh);
                ldsm4(bh,     sWh + boff);
                ldsm4(bh + 4, sWh + boff + 16 * TSTRIDE);
            }
#pragma unroll
            for (int mt = 0; mt < 4; mt++) {
                uint32_t ah[4], al[4];
                uint32_t off = (uint32_t)((wm + mt * 16 + arow) * TSTRIDE + acol);
                ldsm4(ah, sAh + off);
                ldsm4(al, sAl + off);
#pragma unroll
                for (int nt = 0; nt < 4; nt++) {
                    mma16816h(acc[mt][nt], ah, bh + nt * 2);
                    mma16816h(acc[mt][nt], al, bh + nt * 2);
                }
            }
        }
        __syncthreads();
    }

    const int r0 = lane >> 2;
    const int c0 = (lane & 3) * 2;
#pragma unroll
    for (int mt = 0; mt < 4; mt++) {
#pragma unroll
        for (int nt = 0; nt < 4; nt++) {
            int gm = m0 + wm + mt * 16 + r0;
            int gn = n0 + wn + nt * 8 + c0;
            float2 bv = *(const float2*)(bias + gn);
            float2 o0, o1;
            o0.x = acc[mt][nt][0] + bv.x;
            o0.y = acc[mt][nt][1] + bv.y;
            o1.x = acc[mt][nt][2] + bv.x;
            o1.y = acc[mt][nt][3] + bv.y;
            *(float2*)(C + (size_t)gm * DIM + gn) = o0;
            *(float2*)(C + (size_t)(gm + 8) * DIM + gn) = o1;
        }
    }
}

// ---------------- pack: rope + scale + split + per-head relayout (bf16) -----
__global__ void pack_qkv(const float* __restrict__ cosb,
                         const float* __restrict__ sinb)
{
    const int s = blockIdx.x;
    const int tid = threadIdx.x;
    const float scale = 0.11180339887498949f;

    for (int p = tid; p < NH * 20; p += 256) {
        int h = p / 20, dp = (p % 20) * 2;
        float2 c2 = *(const float2*)(cosb + s * HD + dp);
        float2 s2 = *(const float2*)(sinb + s * HD + dp);
        size_t ib = (size_t)s * DIM + h * HD + dp;
        size_t ob = ((size_t)h * S + s) * HD + dp;

        float2 qa = *(const float2*)(g_q + ib);
        float2 qb = *(const float2*)(g_q + ib + 40);
        float q1x = (qa.x * c2.x - qb.x * s2.x) * scale;
        float q1y = (qa.y * c2.y - qb.y * s2.y) * scale;
        float q2x = (qb.x * c2.x + qa.x * s2.x) * scale;
        float q2y = (qb.y * c2.y + qa.y * s2.y) * scale;
        uint32_t lo, hi;
        hi = pk2(q1x, q1y, lo);
        *(uint32_t*)(g_qh + ob) = hi;      *(uint32_t*)(g_ql + ob) = lo;
        hi = pk2(q2x, q2y, lo);
        *(uint32_t*)(g_qh + ob + 40) = hi; *(uint32_t*)(g_ql + ob + 40) = lo;

        float2 ka = *(const float2*)(g_k + ib);
        float2 kb = *(const float2*)(g_k + ib + 40);
        float k1x = ka.x * c2.x - kb.x * s2.x;
        float k1y = ka.y * c2.y - kb.y * s2.y;
        float k2x = kb.x * c2.x + ka.x * s2.x;
        float k2y = kb.y * c2.y + ka.y * s2.y;
        hi = pk2(k1x, k1y, lo);
        *(uint32_t*)(g_kh + ob) = hi;      *(uint32_t*)(g_kl + ob) = lo;
        hi = pk2(k2x, k2y, lo);
        *(uint32_t*)(g_kh + ob + 40) = hi; *(uint32_t*)(g_kl + ob + 40) = lo;
    }

    for (int p = tid; p < DIM / 2; p += 256) {
        int e = p * 2;
        int h = e / HD, d = e % HD;
        float2 v2 = *(const float2*)(g_v + (size_t)s * DIM + e);
        size_t ob = ((size_t)h * S + s) * HD + d;
        uint32_t lo, hi;
        hi = pk2(v2.x, v2.y, lo);
        *(uint32_t*)(g_vh + ob) = hi;
        *(uint32_t*)(g_vl + ob) = lo;
    }
}

// ---------------- flash attention: register S/P, double-buffered KV ---------
#define ATS 176
#define ATB (64 * ATS)
#define AQH 0
#define AQL ATB
#define AKV0 (2 * ATB)
#define AKV1 (6 * ATB)
#define APMAX (10 * ATB)
#define APLS  (APMAX + 512)
#define ATTN_SMEM (APLS + 256)        // 113408 B

__global__ __launch_bounds__(256, 2) void attn_mma(__half* __restrict__ ch,
                                                   __half* __restrict__ cl)
{
    extern __shared__ char sm[];
    const uint32_t sb = smem_u32(sm);
    const int tid = threadIdx.x;
    const int wid = tid >> 5;
    const int lane = tid & 31;

    const int qt = blockIdx.x;
    const int h  = blockIdx.y;
    const int sg = blockIdx.z;
    const int s0 = sg * SEG;
    const int q0 = s0 + qt * 64;
    const size_t hb = (size_t)h * S * HD;

    const int wm = (wid & 3) * 16;
    const int wh = wid >> 2;
    const int wn = wh * 32;

    float* pmax = (float*)(sm + APMAX);
    float* plsum = (float*)(sm + APLS);

    const char* qhp = (const char*)(g_qh + hb + (size_t)q0 * HD);
    const char* qlp = (const char*)(g_ql + hb + (size_t)q0 * HD);
    const char* khp = (const char*)(g_kh + hb + (size_t)s0 * HD);
    const char* klp = (const char*)(g_kl + hb + (size_t)s0 * HD);
    const char* vhp = (const char*)(g_vh + hb + (size_t)s0 * HD);
    const char* vlp = (const char*)(g_vl + hb + (size_t)s0 * HD);

    auto cp_pair = [&](uint32_t dH, uint32_t dL, const char* srcH, const char* srcL, int rb) {
#pragma unroll
        for (int i = 0; i < 5; i++) {
            int f = i * 256 + tid;
            int sel = f >= 640;
            int g = f - (sel ? 640 : 0);
            int r = g / 10, c = g - r * 10;
            CP_ASYNC16(sb + (sel ? dL : dH) + r * ATS + c * 16,
                       (sel ? srcL : srcH) + (size_t)(rb + r) * 160 + c * 16);
        }
    };

    cp_pair(AQH, AQL, qhp, qlp, 0);
    cp_pair(AKV0, AKV0 + ATB, khp, klp, 0);
    CP_COMMIT();
    cp_pair(AKV0 + 2 * ATB, AKV0 + 3 * ATB, vhp, vlp, 0);
    CP_COMMIT();
    cp_pair(AKV1, AKV1 + ATB, khp, klp, 64);
    CP_COMMIT();
    cp_pair(AKV1 + 2 * ATB, AKV1 + 3 * ATB, vhp, vlp, 64);
    CP_COMMIT();

    float acc[10][4];
#pragma unroll
    for (int nt = 0; nt < 10; nt++)
#pragma unroll
        for (int i = 0; i < 4; i++) acc[nt][i] = 0.f;

    float mold0 = -1e30f, mold1 = -1e30f;
    float lsum0 = 0.f, lsum1 = 0.f;

    const int qrow = wm + (lane & 15);
    const uint32_t qcoloff = (uint32_t)((lane >> 4) * 16);
    const int krowa = wn + ((lane >> 4) << 3) + (lane & 7);
    const uint32_t kcoloff = (uint32_t)(((lane >> 3) & 1) * 16);
    const int r4 = lane >> 2;
    const int q2 = (lane & 3) * 2;

    for (int c = 0; c < 8; c++) {
        const uint32_t kv = sb + ((c & 1) ? AKV1 : AKV0);
        const uint32_t sKH = kv, sKL = kv + ATB, sVH = kv + 2 * ATB, sVL = kv + 3 * ATB;

        if (c == 7) { CP_WAIT1(); } else { CP_WAIT3(); }
        __syncthreads();

        float sa[4][4];
#pragma unroll
        for (int nt = 0; nt < 4; nt++)
#pragma unroll
            for (int i = 0; i < 4; i++) sa[nt][i] = 0.f;

#pragma unroll
        for (int ks = 0; ks < 5; ks++) {
            uint32_t qh4[4], ql4[4], kh[8], kl[8];
            uint32_t qoff = (uint32_t)(qrow * ATS + ks * 32) + qcoloff;
            ldsm4(qh4, sb + AQH + qoff);
            ldsm4(ql4, sb + AQL + qoff);
            uint32_t koff0 = (uint32_t)(krowa * ATS + ks * 32) + kcoloff;
            ldsm4(kh,     sKH + koff0);
            ldsm4(kh + 4, sKH + koff0 + 16 * ATS);
            ldsm4(kl,     sKL + koff0);
            ldsm4(kl + 4, sKL + koff0 + 16 * ATS);
#pragma unroll
            for (int nt = 0; nt < 4; nt++) {
                mma16816(sa[nt], qh4, kh + nt * 2);
                mma16816(sa[nt], qh4, kl + nt * 2);
                mma16816(sa[nt], ql4, kh + nt * 2);
            }
        }

        float mx0 = fmaxf(fmaxf(sa[0][0], sa[0][1]), fmaxf(sa[1][0], sa[1][1]));
        mx0 = fmaxf(mx0, fmaxf(fmaxf(sa[2][0], sa[2][1]), fmaxf(sa[3][0], sa[3][1])));
        float mx1 = fmaxf(fmaxf(sa[0][2], sa[0][3]), fmaxf(sa[1][2], sa[1][3]));
        mx1 = fmaxf(mx1, fmaxf(fmaxf(sa[2][2], sa[2][3]), fmaxf(sa[3][2], sa[3][3])));
        mx0 = fmaxf(mx0, __shfl_xor_sync(0xffffffffu, mx0, 1));
        mx0 = fmaxf(mx0, __shfl_xor_sync(0xffffffffu, mx0, 2));
        mx1 = fmaxf(mx1, __shfl_xor_sync(0xffffffffu, mx1, 1));
        mx1 = fmaxf(mx1, __shfl_xor_sync(0xffffffffu, mx1, 2));
        if ((lane & 3) == 0) {
            pmax[wh * 64 + wm + r4] = mx0;
            pmax[wh * 64 + wm + 8 + r4] = mx1;
        }

        if (c == 7) { CP_WAIT0(); } else { CP_WAIT2(); }
        __syncthreads();

        float ma0 = fmaxf(pmax[wm + r4], pmax[64 + wm + r4]);
        float ma1 = fmaxf(pmax[wm + 8 + r4], pmax[64 + wm + 8 + r4]);
        float mn0 = fmaxf(mold0, ma0);
        float mn1 = fmaxf(mold1, ma1);
        float fs0 = __expf(mold0 - mn0);
        float fs1 = __expf(mold1 - mn1);
        mold0 = mn0; mold1 = mn1;

        float s0r = 0.f, s1r = 0.f;
#pragma unroll
        for (int nt = 0; nt < 4; nt++) {
            sa[nt][0] = __expf(sa[nt][0] - mn0);
            sa[nt][1] = __expf(sa[nt][1] - mn0);
            sa[nt][2] = __expf(sa[nt][2] - mn1);
            sa[nt][3] = __expf(sa[nt][3] - mn1);
            s0r += sa[nt][0] + sa[nt][1];
            s1r += sa[nt][2] + sa[nt][3];
        }
        s0r += __shfl_xor_sync(0xffffffffu, s0r, 1);
        s0r += __shfl_xor_sync(0xffffffffu, s0r, 2);
        s1r += __shfl_xor_sync(0xffffffffu, s1r, 1);
        s1r += __shfl_xor_sync(0xffffffffu, s1r, 2);
        lsum0 = lsum0 * fs0 + s0r;
        lsum1 = lsum1 * fs1 + s1r;

#pragma unroll
        for (int nt = 0; nt < 10; nt++) {
            acc[nt][0] *= fs0; acc[nt][1] *= fs0;
            acc[nt][2] *= fs1; acc[nt][3] *= fs1;
        }

#pragma unroll
        for (int kb = 0; kb < 2; kb++) {
            uint32_t aH[4], aL[4];
            aH[0] = pk2(sa[2 * kb][0], sa[2 * kb][1], aL[0]);
            aH[1] = pk2(sa[2 * kb][2], sa[2 * kb][3], aL[1]);
            aH[2] = pk2(sa[2 * kb + 1][0], sa[2 * kb + 1][1], aL[2]);
            aH[3] = pk2(sa[2 * kb + 1][2], sa[2 * kb + 1][3], aL[3]);
            const int vrow = wn + kb * 16 + (lane & 15);
#pragma unroll
            for (int np = 0; np < 5; np++) {
                uint32_t vh4[4], vl4[4];
                uint32_t voff = (uint32_t)(vrow * ATS + (np * 16 + ((lane >> 4) << 3)) * 2);
                ldsm4t(vh4, sVH + voff);
                ldsm4t(vl4, sVL + voff);
                mma16816(acc[np * 2], aH, vh4);
                mma16816(acc[np * 2], aH, vl4);
                mma16816(acc[np * 2], aL, vh4);
                mma16816(acc[np * 2 + 1], aH, vh4 + 2);
                mma16816(acc[np * 2 + 1], aH, vl4 + 2);
                mma16816(acc[np * 2 + 1], aL, vh4 + 2);
            }
        }
        __syncthreads();

        if (c + 2 < 8) {
            const uint32_t nb = sb + ((c & 1) ? AKV1 : AKV0);
            cp_pair(nb - sb, nb - sb + ATB, khp, klp, (c + 2) * 64);
            CP_COMMIT();
            cp_pair(nb - sb + 2 * ATB, nb - sb + 3 * ATB, vhp, vlp, (c + 2) * 64);
            CP_COMMIT();
        }
    }

    float* cb = (float*)(sm + AKV0);
    if (wh == 1) {
#pragma unroll
        for (int nt = 0; nt < 10; nt++) {
            int cc = nt * 8 + q2;
            cb[(wm + r4) * 80 + cc]     = acc[nt][0];
            cb[(wm + r4) * 80 + cc + 1] = acc[nt][1];
            cb[(wm + r4 + 8) * 80 + cc]     = acc[nt][2];
            cb[(wm + r4 + 8) * 80 + cc + 1] = acc[nt][3];
        }
        if ((lane & 3) == 0) {
            plsum[wm + r4] = lsum0;
            plsum[wm + r4 + 8] = lsum1;
        }
    }
    __syncthreads();
    if (wh == 0) {
        float li0 = 1.f / (lsum0 + plsum[wm + r4]);
        float li1 = 1.f / (lsum1 + plsum[wm + r4 + 8]);
        int gr0 = q0 + wm + r4;
#pragma unroll
        for (int nt = 0; nt < 10; nt++) {
            int col = h * HD + nt * 8 + q2;
            float x0 = (acc[nt][0] + cb[(wm + r4) * 80 + nt * 8 + q2]) * li0;
            float y0 = (acc[nt][1] + cb[(wm + r4) * 80 + nt * 8 + q2 + 1]) * li0;
            float x1 = (acc[nt][2] + cb[(wm + r4 + 8) * 80 + nt * 8 + q2]) * li1;
            float y1 = (acc[nt][3] + cb[(wm + r4 + 8) * 80 + nt * 8 + q2 + 1]) * li1;
            size_t a0 = (size_t)gr0 * DIM + col;
            size_t a1 = a0 + (size_t)8 * DIM;
            uint32_t lo;
            uint32_t hi = pk2h(x0, y0, lo);
            *(uint32_t*)(ch + a0) = hi;
            *(uint32_t*)(cl + a0) = lo;
            hi = pk2h(x1, y1, lo);
            *(uint32_t*)(ch + a1) = hi;
            *(uint32_t*)(cl + a1) = lo;
        }
    }
}

// ---------------------------------------------------------------------------
extern "C" void kernel_launch(void* const* d_in, const int* in_sizes, int n_in,
                              void* d_out, int out_size)
{
    const float* hs   = (const float*)d_in[0];
    const float* cosb = (const float*)d_in[1];
    const float* sinb = (const float*)d_in[2];
    const float* wq   = (const float*)d_in[3];
    const float* bq   = (const float*)d_in[4];
    const float* wk   = (const float*)d_in[5];
    const float* bk   = (const float*)d_in[6];
    const float* wv   = (const float*)d_in[7];
    const float* bv   = (const float*)d_in[8];
    const float* wo   = (const float*)d_in[9];
    const float* bo   = (const float*)d_in[10];
    float* out = (float*)d_out;

    float *qp, *kp, *vp;
    cudaGetSymbolAddress((void**)&qp, g_q);
    cudaGetSymbolAddress((void**)&kp, g_k);
    cudaGetSymbolAddress((void**)&vp, g_v);
    __half *ah, *al, *wh, *ch, *cl;
    cudaGetSymbolAddress((void**)&ah, g_ah);
    cudaGetSymbolAddress((void**)&al, g_al);
    cudaGetSymbolAddress((void**)&wh, g_wh);
    cudaGetSymbolAddress((void**)&ch, g_ch);
    cudaGetSymbolAddress((void**)&cl, g_cl);

    cudaFuncSetAttribute(gemm_hmma,
                         cudaFuncAttributeMaxDynamicSharedMemorySize, GEMM_SMEM);
    cudaFuncSetAttribute(attn_mma,
                         cudaFuncAttributeMaxDynamicSharedMemorySize, ATTN_SMEM);

    split_hs<<<(S * DIM / 4) / 256, 256>>>((const float4*)hs, (uint2*)ah, (uint2*)al,
                                           S * DIM / 4);
    split_w4<<<dim3((DIM * DIM / 4) / 256, 4), 256>>>(
        (const float4*)wq, (const float4*)wk, (const float4*)wv, (const float4*)wo,
        (uint2*)wh);

    gemm_hmma<<<dim3(DIM / GBN, S / GBM, 3), 256, GEMM_SMEM>>>(
        ah, al, wh, 0, bq, bk, bv, qp, kp, vp);

    pack_qkv<<<S, 256>>>(cosb, sinb);

    attn_mma<<<dim3(8, NH, NSEG), 256, ATTN_SMEM>>>(ch, cl);

    gemm_hmma<<<dim3(DIM / GBN, S / GBM, 1), 256, GEMM_SMEM>>>(
        ch, cl, wh, 3, bo, bo, bo, out, out, out);
}

// round 13
// speedup vs baseline: 1.4692x; 1.1034x over previous
#include <cuda_runtime.h>
#include <cuda_bf16.h>
#include <cuda_fp16.h>
#include <cstdint>
#include <math.h>

#define S    3072
#define DIM  1280
#define NH   16
#define HD   80
#define SEG  512
#define NSEG 6

// ---------------- scratch (__device__ globals; no allocs allowed) ----------
__device__ float g_q[S * DIM];
__device__ float g_k[S * DIM];
__device__ float g_v[S * DIM];

__device__ __half g_ah[S * DIM];              // hidden hi (fp16)
__device__ __half g_al[S * DIM];              // hidden lo (fp16)
__device__ __half g_wh[4 * DIM * DIM];        // weights hi only (fp16)
__device__ __half g_ch[S * DIM];              // ctx hi
__device__ __half g_cl[S * DIM];              // ctx lo

// attention operands (fp16): q hi/lo, k hi only, v hi only
__device__ __half g_qh[NH * S * HD];
__device__ __half g_ql[NH * S * HD];
__device__ __half g_kh[NH * S * HD];
__device__ __half g_vh[NH * S * HD];

// ---------------- PTX helpers (sm_80-era, arch-neutral) --------------------
__device__ __forceinline__ uint32_t smem_u32(const void* p) {
    uint32_t a;
    asm("{ .reg .u64 t; cvta.to.shared.u64 t, %1; cvt.u32.u64 %0, t; }"
        : "=r"(a) : "l"(p));
    return a;
}
__device__ __forceinline__ void ldsm4(uint32_t* r, uint32_t addr) {
    asm volatile("ldmatrix.sync.aligned.m8n8.x4.shared.b16 {%0,%1,%2,%3}, [%4];"
                 : "=r"(r[0]), "=r"(r[1]), "=r"(r[2]), "=r"(r[3]) : "r"(addr));
}
__device__ __forceinline__ void ldsm4t(uint32_t* r, uint32_t addr) {
    asm volatile("ldmatrix.sync.aligned.m8n8.x4.trans.shared.b16 {%0,%1,%2,%3}, [%4];"
                 : "=r"(r[0]), "=r"(r[1]), "=r"(r[2]), "=r"(r[3]) : "r"(addr));
}
// fp16 MMA
__device__ __forceinline__ void mma16816h(float* d, const uint32_t* a, const uint32_t* b) {
    asm volatile(
        "mma.sync.aligned.m16n8k16.row.col.f32.f16.f16.f32 "
        "{%0,%1,%2,%3}, {%4,%5,%6,%7}, {%8,%9}, {%0,%1,%2,%3};"
        : "+f"(d[0]), "+f"(d[1]), "+f"(d[2]), "+f"(d[3])
        : "r"(a[0]), "r"(a[1]), "r"(a[2]), "r"(a[3]), "r"(b[0]), "r"(b[1]));
}

#define CP_ASYNC16(dst, src) \
    asm volatile("cp.async.cg.shared.global [%0], [%1], 16;" :: "r"(dst), "l"(src))
#define CP_COMMIT() asm volatile("cp.async.commit_group;")
#define CP_WAIT3()  asm volatile("cp.async.wait_group 3;")
#define CP_WAIT2()  asm volatile("cp.async.wait_group 2;")
#define CP_WAIT1()  asm volatile("cp.async.wait_group 1;")
#define CP_WAIT0()  asm volatile("cp.async.wait_group 0;")

// fp16 hi/lo pack
__device__ __forceinline__ uint32_t pk2h(float x, float y, uint32_t& lo) {
    __half hx = __float2half_rn(x), hy = __float2half_rn(y);
    __half lx = __float2half_rn(x - __half2float(hx));
    __half ly = __float2half_rn(y - __half2float(hy));
    __half2 H = __halves2half2(hx, hy), L = __halves2half2(lx, ly);
    lo = *(uint32_t*)&L;
    return *(uint32_t*)&H;
}
__device__ __forceinline__ uint32_t pkh(float x, float y) {
    __half2 H = __halves2half2(__float2half_rn(x), __float2half_rn(y));
    return *(uint32_t*)&H;
}

// ---------------- fp32 -> fp16 hi/lo splits ---------------------------------
__global__ void split_hs(const float4* __restrict__ src,
                         uint2* __restrict__ hi, uint2* __restrict__ lo, int n4) {
    int i = blockIdx.x * blockDim.x + threadIdx.x;
    if (i < n4) {
        float4 v = src[i];
        uint32_t l0, l1;
        uint32_t h0 = pk2h(v.x, v.y, l0);
        uint32_t h1 = pk2h(v.z, v.w, l1);
        hi[i] = make_uint2(h0, h1);
        lo[i] = make_uint2(l0, l1);
    }
}

__global__ void split_w4(const float4* __restrict__ s0, const float4* __restrict__ s1,
                         const float4* __restrict__ s2, const float4* __restrict__ s3,
                         uint2* __restrict__ hi) {
    int z = blockIdx.y;
    const float4* s = (z == 0) ? s0 : (z == 1) ? s1 : (z == 2) ? s2 : s3;
    size_t base = (size_t)z * (DIM * DIM / 4);
    int i = blockIdx.x * blockDim.x + threadIdx.x;
    float4 v = s[i];
    hi[base + i] = make_uint2(pkh(v.x, v.y), pkh(v.z, v.w));
}

// ---------------- HMMA fp16x2 GEMM, BK=64 (unchanged from R12) --------------
#define GBM 128
#define GBN 128
#define NCHUNK (DIM / 64)            // 20
#define TSTRIDE 144
#define TILE_B  (128 * TSTRIDE)
#define STAGE_B (3 * TILE_B)
#define GEMM_SMEM (2 * STAGE_B)      // 110592

__global__ __launch_bounds__(256, 2) void gemm_hmma(
    const __half* __restrict__ Ahi, const __half* __restrict__ Alo,
    const __half* __restrict__ Wh_base,
    int zoff,
    const float* __restrict__ bias0, const float* __restrict__ bias1, const float* __restrict__ bias2,
    float* __restrict__ C0, float* __restrict__ C1, float* __restrict__ C2)
{
    extern __shared__ char smem[];
    const uint32_t sb = smem_u32(smem);
    const int tid  = threadIdx.x;
    const int wid  = tid >> 5;
    const int lane = tid & 31;

    const int z = blockIdx.z;
    const __half* Wh = Wh_base + (size_t)(zoff + z) * DIM * DIM;
    const float* bias = (z == 0) ? bias0 : (z == 1) ? bias1 : bias2;
    float* C = (z == 0) ? C0 : (z == 1) ? C1 : C2;

    const int m0 = blockIdx.y * GBM;
    const int n0 = blockIdx.x * GBN;
    const int wm = (wid & 1) * 64;
    const int wn = (wid >> 1) * 32;

    const char* srcs[3];
    srcs[0] = (const char*)(Ahi + (size_t)m0 * DIM);
    srcs[1] = (const char*)(Alo + (size_t)m0 * DIM);
    srcs[2] = (const char*)(Wh  + (size_t)n0 * DIM);

    float acc[4][4][4];
#pragma unroll
    for (int mt = 0; mt < 4; mt++)
#pragma unroll
        for (int nt = 0; nt < 4; nt++)
#pragma unroll
            for (int i = 0; i < 4; i++) acc[mt][nt][i] = 0.f;

    {
#pragma unroll
        for (int i = 0; i < 12; i++) {
            int t = i >> 2;
            int e = (i & 3) * 256 + tid;
            int row = e >> 3, c16 = e & 7;
            CP_ASYNC16(sb + t * TILE_B + row * TSTRIDE + c16 * 16,
                       srcs[t] + (size_t)row * (DIM * 2) + c16 * 16);
        }
        CP_COMMIT();
    }

    const int arow = lane & 15;
    const int acolh = (lane >> 4) * 16;
    const int browa = ((lane >> 4) << 3) + (lane & 7);
    const int bcolh = ((lane >> 3) & 1) * 16;

    for (int c = 0; c < NCHUNK; c++) {
        if (c + 1 < NCHUNK) {
            const int k0b = (c + 1) * 128;
            uint32_t d = sb + ((c + 1) & 1) * STAGE_B;
#pragma unroll
            for (int i = 0; i < 12; i++) {
                int t = i >> 2;
                int e = (i & 3) * 256 + tid;
                int row = e >> 3, c16 = e & 7;
                CP_ASYNC16(d + t * TILE_B + row * TSTRIDE + c16 * 16,
                           srcs[t] + (size_t)row * (DIM * 2) + k0b + c16 * 16);
            }
            CP_COMMIT();
            CP_WAIT1();
        } else {
            CP_WAIT0();
        }
        __syncthreads();

        const uint32_t stage = sb + (c & 1) * STAGE_B;
        const uint32_t sAh = stage;
        const uint32_t sAl = stage + TILE_B;
        const uint32_t sWh = stage + 2 * TILE_B;

#pragma unroll
        for (int ks = 0; ks < 4; ks++) {
            const int acol = ks * 32 + acolh;
            uint32_t bh[8];
            {
                uint32_t boff = (uint32_t)((wn + browa) * TSTRIDE + ks * 32 + bcolh);
                ldsm4(bh,     sWh + boff);
                ldsm4(bh + 4, sWh + boff + 16 * TSTRIDE);
            }
#pragma unroll
            for (int mt = 0; mt < 4; mt++) {
                uint32_t ah[4], al[4];
                uint32_t off = (uint32_t)((wm + mt * 16 + arow) * TSTRIDE + acol);
                ldsm4(ah, sAh + off);
                ldsm4(al, sAl + off);
#pragma unroll
                for (int nt = 0; nt < 4; nt++) {
                    mma16816h(acc[mt][nt], ah, bh + nt * 2);
                    mma16816h(acc[mt][nt], al, bh + nt * 2);
                }
            }
        }
        __syncthreads();
    }

    const int r0 = lane >> 2;
    const int c0 = (lane & 3) * 2;
#pragma unroll
    for (int mt = 0; mt < 4; mt++) {
#pragma unroll
        for (int nt = 0; nt < 4; nt++) {
            int gm = m0 + wm + mt * 16 + r0;
            int gn = n0 + wn + nt * 8 + c0;
            float2 bv = *(const float2*)(bias + gn);
            float2 o0, o1;
            o0.x = acc[mt][nt][0] + bv.x;
            o0.y = acc[mt][nt][1] + bv.y;
            o1.x = acc[mt][nt][2] + bv.x;
            o1.y = acc[mt][nt][3] + bv.y;
            *(float2*)(C + (size_t)gm * DIM + gn) = o0;
            *(float2*)(C + (size_t)(gm + 8) * DIM + gn) = o1;
        }
    }
}

// ---------------- pack: rope + scale + split + per-head relayout (fp16) -----
__global__ void pack_qkv(const float* __restrict__ cosb,
                         const float* __restrict__ sinb)
{
    const int s = blockIdx.x;
    const int tid = threadIdx.x;
    const float scale = 0.11180339887498949f;

    for (int p = tid; p < NH * 20; p += 256) {
        int h = p / 20, dp = (p % 20) * 2;
        float2 c2 = *(const float2*)(cosb + s * HD + dp);
        float2 s2 = *(const float2*)(sinb + s * HD + dp);
        size_t ib = (size_t)s * DIM + h * HD + dp;
        size_t ob = ((size_t)h * S + s) * HD + dp;

        float2 qa = *(const float2*)(g_q + ib);
        float2 qb = *(const float2*)(g_q + ib + 40);
        float q1x = (qa.x * c2.x - qb.x * s2.x) * scale;
        float q1y = (qa.y * c2.y - qb.y * s2.y) * scale;
        float q2x = (qb.x * c2.x + qa.x * s2.x) * scale;
        float q2y = (qb.y * c2.y + qa.y * s2.y) * scale;
        uint32_t lo, hi;
        hi = pk2h(q1x, q1y, lo);
        *(uint32_t*)(g_qh + ob) = hi;      *(uint32_t*)(g_ql + ob) = lo;
        hi = pk2h(q2x, q2y, lo);
        *(uint32_t*)(g_qh + ob + 40) = hi; *(uint32_t*)(g_ql + ob + 40) = lo;

        float2 ka = *(const float2*)(g_k + ib);
        float2 kb = *(const float2*)(g_k + ib + 40);
        float k1x = ka.x * c2.x - kb.x * s2.x;
        float k1y = ka.y * c2.y - kb.y * s2.y;
        float k2x = kb.x * c2.x + ka.x * s2.x;
        float k2y = kb.y * c2.y + ka.y * s2.y;
        *(uint32_t*)(g_kh + ob)      = pkh(k1x, k1y);
        *(uint32_t*)(g_kh + ob + 40) = pkh(k2x, k2y);
    }

    for (int p = tid; p < DIM / 2; p += 256) {
        int e = p * 2;
        int h = e / HD, d = e % HD;
        float2 v2 = *(const float2*)(g_v + (size_t)s * DIM + e);
        size_t ob = ((size_t)h * S + s) * HD + d;
        *(uint32_t*)(g_vh + ob) = pkh(v2.x, v2.y);
    }
}

// ---------------- flash attention: fp16x2, register S/P ---------------------
// Tiles: Q hi, Q lo, K0, V0, K1, V1 (each 64 x 160B, stride 176)
#define ATS 176
#define ATB (64 * ATS)               // 11264
#define AQH 0
#define AQL ATB
#define AK0 (2 * ATB)
#define AV0 (3 * ATB)
#define AK1 (4 * ATB)
#define AV1 (5 * ATB)
#define APMAX (6 * ATB)
#define APLS  (APMAX + 512)
#define ATTN_SMEM (APLS + 256)       // 68352 B

__global__ __launch_bounds__(256, 2) void attn_mma(__half* __restrict__ ch,
                                                   __half* __restrict__ cl)
{
    extern __shared__ char sm[];
    const uint32_t sb = smem_u32(sm);
    const int tid = threadIdx.x;
    const int wid = tid >> 5;
    const int lane = tid & 31;

    const int qt = blockIdx.x;
    const int h  = blockIdx.y;
    const int sg = blockIdx.z;
    const int s0 = sg * SEG;
    const int q0 = s0 + qt * 64;
    const size_t hb = (size_t)h * S * HD;

    const int wm = (wid & 3) * 16;
    const int wh = wid >> 2;
    const int wn = wh * 32;

    float* pmax = (float*)(sm + APMAX);
    float* plsum = (float*)(sm + APLS);

    const char* qhp = (const char*)(g_qh + hb + (size_t)q0 * HD);
    const char* qlp = (const char*)(g_ql + hb + (size_t)q0 * HD);
    const char* khp = (const char*)(g_kh + hb + (size_t)s0 * HD);
    const char* vhp = (const char*)(g_vh + hb + (size_t)s0 * HD);

    // Q: two tiles (hi/lo), 1280 cp16
    {
#pragma unroll
        for (int i = 0; i < 5; i++) {
            int f = i * 256 + tid;
            int sel = f >= 640;
            int g = f - (sel ? 640 : 0);
            int r = g / 10, c = g - r * 10;
            CP_ASYNC16(sb + (sel ? AQL : AQH) + r * ATS + c * 16,
                       (sel ? qlp : qhp) + (size_t)r * 160 + c * 16);
        }
    }
    // single-tile KV loader (640 cp16)
    auto cp_tile = [&](uint32_t dst, const char* src, int rb) {
#pragma unroll
        for (int i = 0; i < 3; i++) {
            int f = i * 256 + tid;
            if (f < 640) {
                int r = f / 10, c = f - r * 10;
                CP_ASYNC16(sb + dst + r * ATS + c * 16,
                           src + (size_t)(rb + r) * 160 + c * 16);
            }
        }
    };

    cp_tile(AK0, khp, 0);
    CP_COMMIT();                       // group: Q + K0
    cp_tile(AV0, vhp, 0);
    CP_COMMIT();                       // V0
    cp_tile(AK1, khp, 64);
    CP_COMMIT();                       // K1
    cp_tile(AV1, vhp, 64);
    CP_COMMIT();                       // V1

    float acc[10][4];
#pragma unroll
    for (int nt = 0; nt < 10; nt++)
#pragma unroll
        for (int i = 0; i < 4; i++) acc[nt][i] = 0.f;

    float mold0 = -1e30f, mold1 = -1e30f;
    float lsum0 = 0.f, lsum1 = 0.f;

    const int qrow = wm + (lane & 15);
    const uint32_t qcoloff = (uint32_t)((lane >> 4) * 16);
    const int krowa = wn + ((lane >> 4) << 3) + (lane & 7);
    const uint32_t kcoloff = (uint32_t)(((lane >> 3) & 1) * 16);
    const int r4 = lane >> 2;
    const int q2 = (lane & 3) * 2;

    for (int c = 0; c < 8; c++) {
        const uint32_t sKH = sb + ((c & 1) ? AK1 : AK0);
        const uint32_t sVH = sb + ((c & 1) ? AV1 : AV0);

        if (c == 7) { CP_WAIT1(); } else { CP_WAIT3(); }
        __syncthreads();

        // ---- S = Q K^T (fp16x2) ----
        float sa[4][4];
#pragma unroll
        for (int nt = 0; nt < 4; nt++)
#pragma unroll
            for (int i = 0; i < 4; i++) sa[nt][i] = 0.f;

#pragma unroll
        for (int ks = 0; ks < 5; ks++) {
            uint32_t qh4[4], ql4[4], kh[8];
            uint32_t qoff = (uint32_t)(qrow * ATS + ks * 32) + qcoloff;
            ldsm4(qh4, sb + AQH + qoff);
            ldsm4(ql4, sb + AQL + qoff);
            uint32_t koff0 = (uint32_t)(krowa * ATS + ks * 32) + kcoloff;
            ldsm4(kh,     sKH + koff0);
            ldsm4(kh + 4, sKH + koff0 + 16 * ATS);
#pragma unroll
            for (int nt = 0; nt < 4; nt++) {
                mma16816h(sa[nt], qh4, kh + nt * 2);
                mma16816h(sa[nt], ql4, kh + nt * 2);
            }
        }

        float mx0 = fmaxf(fmaxf(sa[0][0], sa[0][1]), fmaxf(sa[1][0], sa[1][1]));
        mx0 = fmaxf(mx0, fmaxf(fmaxf(sa[2][0], sa[2][1]), fmaxf(sa[3][0], sa[3][1])));
        float mx1 = fmaxf(fmaxf(sa[0][2], sa[0][3]), fmaxf(sa[1][2], sa[1][3]));
        mx1 = fmaxf(mx1, fmaxf(fmaxf(sa[2][2], sa[2][3]), fmaxf(sa[3][2], sa[3][3])));
        mx0 = fmaxf(mx0, __shfl_xor_sync(0xffffffffu, mx0, 1));
        mx0 = fmaxf(mx0, __shfl_xor_sync(0xffffffffu, mx0, 2));
        mx1 = fmaxf(mx1, __shfl_xor_sync(0xffffffffu, mx1, 1));
        mx1 = fmaxf(mx1, __shfl_xor_sync(0xffffffffu, mx1, 2));
        if ((lane & 3) == 0) {
            pmax[wh * 64 + wm + r4] = mx0;
            pmax[wh * 64 + wm + 8 + r4] = mx1;
        }

        if (c == 7) { CP_WAIT0(); } else { CP_WAIT2(); }
        __syncthreads();

        float ma0 = fmaxf(pmax[wm + r4], pmax[64 + wm + r4]);
        float ma1 = fmaxf(pmax[wm + 8 + r4], pmax[64 + wm + 8 + r4]);
        float mn0 = fmaxf(mold0, ma0);
        float mn1 = fmaxf(mold1, ma1);
        float fs0 = __expf(mold0 - mn0);
        float fs1 = __expf(mold1 - mn1);
        mold0 = mn0; mold1 = mn1;

        float s0r = 0.f, s1r = 0.f;
#pragma unroll
        for (int nt = 0; nt < 4; nt++) {
            sa[nt][0] = __expf(sa[nt][0] - mn0);
            sa[nt][1] = __expf(sa[nt][1] - mn0);
            sa[nt][2] = __expf(sa[nt][2] - mn1);
            sa[nt][3] = __expf(sa[nt][3] - mn1);
            s0r += sa[nt][0] + sa[nt][1];
            s1r += sa[nt][2] + sa[nt][3];
        }
        s0r += __shfl_xor_sync(0xffffffffu, s0r, 1);
        s0r += __shfl_xor_sync(0xffffffffu, s0r, 2);
        s1r += __shfl_xor_sync(0xffffffffu, s1r, 1);
        s1r += __shfl_xor_sync(0xffffffffu, s1r, 2);
        lsum0 = lsum0 * fs0 + s0r;
        lsum1 = lsum1 * fs1 + s1r;

#pragma unroll
        for (int nt = 0; nt < 10; nt++) {
            acc[nt][0] *= fs0; acc[nt][1] *= fs0;
            acc[nt][2] *= fs1; acc[nt][3] *= fs1;
        }

        // ---- PV over this warp's k-half (fp16x2: p hi/lo, v hi) ----
#pragma unroll
        for (int kb = 0; kb < 2; kb++) {
            uint32_t aH[4], aL[4];
            aH[0] = pk2h(sa[2 * kb][0], sa[2 * kb][1], aL[0]);
            aH[1] = pk2h(sa[2 * kb][2], sa[2 * kb][3], aL[1]);
            aH[2] = pk2h(sa[2 * kb + 1][0], sa[2 * kb + 1][1], aL[2]);
            aH[3] = pk2h(sa[2 * kb + 1][2], sa[2 * kb + 1][3], aL[3]);
            const int vrow = wn + kb * 16 + (lane & 15);
#pragma unroll
            for (int np = 0; np < 5; np++) {
                uint32_t vh4[4];
                uint32_t voff = (uint32_t)(vrow * ATS + (np * 16 + ((lane >> 4) << 3)) * 2);
                ldsm4t(vh4, sVH + voff);
                mma16816h(acc[np * 2], aH, vh4);
                mma16816h(acc[np * 2], aL, vh4);
                mma16816h(acc[np * 2 + 1], aH, vh4 + 2);
                mma16816h(acc[np * 2 + 1], aL, vh4 + 2);
            }
        }
        __syncthreads();

        if (c + 2 < 8) {
            cp_tile((c & 1) ? AK1 : AK0, khp, (c + 2) * 64);
            CP_COMMIT();
            cp_tile((c & 1) ? AV1 : AV0, vhp, (c + 2) * 64);
            CP_COMMIT();
        }
    }

    // ---- epilogue: combine column halves, normalize, write ctx hi/lo -------
    float* cb = (float*)(sm + AK0);
    if (wh == 1) {
#pragma unroll
        for (int nt = 0; nt < 10; nt++) {
            int cc = nt * 8 + q2;
            cb[(wm + r4) * 80 + cc]     = acc[nt][0];
            cb[(wm + r4) * 80 + cc + 1] = acc[nt][1];
            cb[(wm + r4 + 8) * 80 + cc]     = acc[nt][2];
            cb[(wm + r4 + 8) * 80 + cc + 1] = acc[nt][3];
        }
        if ((lane & 3) == 0) {
            plsum[wm + r4] = lsum0;
            plsum[wm + r4 + 8] = lsum1;
        }
    }
    __syncthreads();
    if (wh == 0) {
        float li0 = 1.f / (lsum0 + plsum[wm + r4]);
        float li1 = 1.f / (lsum1 + plsum[wm + r4 + 8]);
        int gr0 = q0 + wm + r4;
#pragma unroll
        for (int nt = 0; nt < 10; nt++) {
            int col = h * HD + nt * 8 + q2;
            float x0 = (acc[nt][0] + cb[(wm + r4) * 80 + nt * 8 + q2]) * li0;
            float y0 = (acc[nt][1] + cb[(wm + r4) * 80 + nt * 8 + q2 + 1]) * li0;
            float x1 = (acc[nt][2] + cb[(wm + r4 + 8) * 80 + nt * 8 + q2]) * li1;
            float y1 = (acc[nt][3] + cb[(wm + r4 + 8) * 80 + nt * 8 + q2 + 1]) * li1;
            size_t a0 = (size_t)gr0 * DIM + col;
            size_t a1 = a0 + (size_t)8 * DIM;
            uint32_t lo;
            uint32_t hi = pk2h(x0, y0, lo);
            *(uint32_t*)(ch + a0) = hi;
            *(uint32_t*)(cl + a0) = lo;
            hi = pk2h(x1, y1, lo);
            *(uint32_t*)(ch + a1) = hi;
            *(uint32_t*)(cl + a1) = lo;
        }
    }
}

// ---------------------------------------------------------------------------
extern "C" void kernel_launch(void* const* d_in, const int* in_sizes, int n_in,
                              void* d_out, int out_size)
{
    const float* hs   = (const float*)d_in[0];
    const float* cosb = (const float*)d_in[1];
    const float* sinb = (const float*)d_in[2];
    const float* wq   = (const float*)d_in[3];
    const float* bq   = (const float*)d_in[4];
    const float* wk   = (const float*)d_in[5];
    const float* bk   = (const float*)d_in[6];
    const float* wv   = (const float*)d_in[7];
    const float* bv   = (const float*)d_in[8];
    const float* wo   = (const float*)d_in[9];
    const float* bo   = (const float*)d_in[10];
    float* out = (float*)d_out;

    float *qp, *kp, *vp;
    cudaGetSymbolAddress((void**)&qp, g_q);
    cudaGetSymbolAddress((void**)&kp, g_k);
    cudaGetSymbolAddress((void**)&vp, g_v);
    __half *ah, *al, *wh, *ch, *cl;
    cudaGetSymbolAddress((void**)&ah, g_ah);
    cudaGetSymbolAddress((void**)&al, g_al);
    cudaGetSymbolAddress((void**)&wh, g_wh);
    cudaGetSymbolAddress((void**)&ch, g_ch);
    cudaGetSymbolAddress((void**)&cl, g_cl);

    cudaFuncSetAttribute(gemm_hmma,
                         cudaFuncAttributeMaxDynamicSharedMemorySize, GEMM_SMEM);
    cudaFuncSetAttribute(attn_mma,
                         cudaFuncAttributeMaxDynamicSharedMemorySize, ATTN_SMEM);

    split_hs<<<(S * DIM / 4) / 256, 256>>>((const float4*)hs, (uint2*)ah, (uint2*)al,
                                           S * DIM / 4);
    split_w4<<<dim3((DIM * DIM / 4) / 256, 4), 256>>>(
        (const float4*)wq, (const float4*)wk, (const float4*)wv, (const float4*)wo,
        (uint2*)wh);

    gemm_hmma<<<dim3(DIM / GBN, S / GBM, 3), 256, GEMM_SMEM>>>(
        ah, al, wh, 0, bq, bk, bv, qp, kp, vp);

    pack_qkv<<<S, 256>>>(cosb, sinb);

    attn_mma<<<dim3(8, NH, NSEG), 256, ATTN_SMEM>>>(ch, cl);

    gemm_hmma<<<dim3(DIM / GBN, S / GBM, 1), 256, GEMM_SMEM>>>(
        ch, cl, wh, 3, bo, bo, bo, out, out, out);
}

// round 14
// speedup vs baseline: 1.5429x; 1.0502x over previous
#include <cuda_runtime.h>
#include <cuda_bf16.h>
#include <cuda_fp16.h>
#include <cstdint>
#include <math.h>

#define S    3072
#define DIM  1280
#define NH   16
#define HD   80
#define SEG  512
#define NSEG 6

// ---------------- scratch (__device__ globals; no allocs allowed) ----------
__device__ float g_q[S * DIM];
__device__ float g_k[S * DIM];
__device__ float g_v[S * DIM];

__device__ __half g_ah[S * DIM];              // hidden hi (fp16)
__device__ __half g_al[S * DIM];              // hidden lo (fp16)
__device__ __half g_wh[4 * DIM * DIM];        // weights hi only (fp16)
__device__ __half g_ch[S * DIM];              // ctx hi
__device__ __half g_cl[S * DIM];              // ctx lo

// attention operands (fp16, hi only)
__device__ __half g_qh[NH * S * HD];
__device__ __half g_kh[NH * S * HD];
__device__ __half g_vh[NH * S * HD];

// ---------------- PTX helpers (sm_80-era, arch-neutral) --------------------
__device__ __forceinline__ uint32_t smem_u32(const void* p) {
    uint32_t a;
    asm("{ .reg .u64 t; cvta.to.shared.u64 t, %1; cvt.u32.u64 %0, t; }"
        : "=r"(a) : "l"(p));
    return a;
}
__device__ __forceinline__ void ldsm4(uint32_t* r, uint32_t addr) {
    asm volatile("ldmatrix.sync.aligned.m8n8.x4.shared.b16 {%0,%1,%2,%3}, [%4];"
                 : "=r"(r[0]), "=r"(r[1]), "=r"(r[2]), "=r"(r[3]) : "r"(addr));
}
__device__ __forceinline__ void ldsm4t(uint32_t* r, uint32_t addr) {
    asm volatile("ldmatrix.sync.aligned.m8n8.x4.trans.shared.b16 {%0,%1,%2,%3}, [%4];"
                 : "=r"(r[0]), "=r"(r[1]), "=r"(r[2]), "=r"(r[3]) : "r"(addr));
}
__device__ __forceinline__ void mma16816h(float* d, const uint32_t* a, const uint32_t* b) {
    asm volatile(
        "mma.sync.aligned.m16n8k16.row.col.f32.f16.f16.f32 "
        "{%0,%1,%2,%3}, {%4,%5,%6,%7}, {%8,%9}, {%0,%1,%2,%3};"
        : "+f"(d[0]), "+f"(d[1]), "+f"(d[2]), "+f"(d[3])
        : "r"(a[0]), "r"(a[1]), "r"(a[2]), "r"(a[3]), "r"(b[0]), "r"(b[1]));
}

#define CP_ASYNC16(dst, src) \
    asm volatile("cp.async.cg.shared.global [%0], [%1], 16;" :: "r"(dst), "l"(src))
#define CP_COMMIT() asm volatile("cp.async.commit_group;")
#define CP_WAIT3()  asm volatile("cp.async.wait_group 3;")
#define CP_WAIT2()  asm volatile("cp.async.wait_group 2;")
#define CP_WAIT1()  asm volatile("cp.async.wait_group 1;")
#define CP_WAIT0()  asm volatile("cp.async.wait_group 0;")

// fp16 hi/lo pack
__device__ __forceinline__ uint32_t pk2h(float x, float y, uint32_t& lo) {
    __half hx = __float2half_rn(x), hy = __float2half_rn(y);
    __half lx = __float2half_rn(x - __half2float(hx));
    __half ly = __float2half_rn(y - __half2float(hy));
    __half2 H = __halves2half2(hx, hy), L = __halves2half2(lx, ly);
    lo = *(uint32_t*)&L;
    return *(uint32_t*)&H;
}
__device__ __forceinline__ uint32_t pkh(float x, float y) {
    __half2 H = __halves2half2(__float2half_rn(x), __float2half_rn(y));
    return *(uint32_t*)&H;
}

// ---------------- fp32 -> fp16 hi/lo splits ---------------------------------
__global__ void split_hs(const float4* __restrict__ src,
                         uint2* __restrict__ hi, uint2* __restrict__ lo, int n4) {
    int i = blockIdx.x * blockDim.x + threadIdx.x;
    if (i < n4) {
        float4 v = src[i];
        uint32_t l0, l1;
        uint32_t h0 = pk2h(v.x, v.y, l0);
        uint32_t h1 = pk2h(v.z, v.w, l1);
        hi[i] = make_uint2(h0, h1);
        lo[i] = make_uint2(l0, l1);
    }
}

__global__ void split_w4(const float4* __restrict__ s0, const float4* __restrict__ s1,
                         const float4* __restrict__ s2, const float4* __restrict__ s3,
                         uint2* __restrict__ hi) {
    int z = blockIdx.y;
    const float4* s = (z == 0) ? s0 : (z == 1) ? s1 : (z == 2) ? s2 : s3;
    size_t base = (size_t)z * (DIM * DIM / 4);
    int i = blockIdx.x * blockDim.x + threadIdx.x;
    float4 v = s[i];
    hi[base + i] = make_uint2(pkh(v.x, v.y), pkh(v.z, v.w));
}

// ---------------- HMMA fp16x2 GEMM, BK=64 (unchanged) -----------------------
#define GBM 128
#define GBN 128
#define NCHUNK (DIM / 64)            // 20
#define TSTRIDE 144
#define TILE_B  (128 * TSTRIDE)
#define STAGE_B (3 * TILE_B)
#define GEMM_SMEM (2 * STAGE_B)      // 110592

__global__ __launch_bounds__(256, 2) void gemm_hmma(
    const __half* __restrict__ Ahi, const __half* __restrict__ Alo,
    const __half* __restrict__ Wh_base,
    int zoff,
    const float* __restrict__ bias0, const float* __restrict__ bias1, const float* __restrict__ bias2,
    float* __restrict__ C0, float* __restrict__ C1, float* __restrict__ C2)
{
    extern __shared__ char smem[];
    const uint32_t sb = smem_u32(smem);
    const int tid  = threadIdx.x;
    const int wid  = tid >> 5;
    const int lane = tid & 31;

    const int z = blockIdx.z;
    const __half* Wh = Wh_base + (size_t)(zoff + z) * DIM * DIM;
    const float* bias = (z == 0) ? bias0 : (z == 1) ? bias1 : bias2;
    float* C = (z == 0) ? C0 : (z == 1) ? C1 : C2;

    const int m0 = blockIdx.y * GBM;
    const int n0 = blockIdx.x * GBN;
    const int wm = (wid & 1) * 64;
    const int wn = (wid >> 1) * 32;

    const char* srcs[3];
    srcs[0] = (const char*)(Ahi + (size_t)m0 * DIM);
    srcs[1] = (const char*)(Alo + (size_t)m0 * DIM);
    srcs[2] = (const char*)(Wh  + (size_t)n0 * DIM);

    float acc[4][4][4];
#pragma unroll
    for (int mt = 0; mt < 4; mt++)
#pragma unroll
        for (int nt = 0; nt < 4; nt++)
#pragma unroll
            for (int i = 0; i < 4; i++) acc[mt][nt][i] = 0.f;

    {
#pragma unroll
        for (int i = 0; i < 12; i++) {
            int t = i >> 2;
            int e = (i & 3) * 256 + tid;
            int row = e >> 3, c16 = e & 7;
            CP_ASYNC16(sb + t * TILE_B + row * TSTRIDE + c16 * 16,
                       srcs[t] + (size_t)row * (DIM * 2) + c16 * 16);
        }
        CP_COMMIT();
    }

    const int arow = lane & 15;
    const int acolh = (lane >> 4) * 16;
    const int browa = ((lane >> 4) << 3) + (lane & 7);
    const int bcolh = ((lane >> 3) & 1) * 16;

    for (int c = 0; c < NCHUNK; c++) {
        if (c + 1 < NCHUNK) {
            const int k0b = (c + 1) * 128;
            uint32_t d = sb + ((c + 1) & 1) * STAGE_B;
#pragma unroll
            for (int i = 0; i < 12; i++) {
                int t = i >> 2;
                int e = (i & 3) * 256 + tid;
                int row = e >> 3, c16 = e & 7;
                CP_ASYNC16(d + t * TILE_B + row * TSTRIDE + c16 * 16,
                           srcs[t] + (size_t)row * (DIM * 2) + k0b + c16 * 16);
            }
            CP_COMMIT();
            CP_WAIT1();
        } else {
            CP_WAIT0();
        }
        __syncthreads();

        const uint32_t stage = sb + (c & 1) * STAGE_B;
        const uint32_t sAh = stage;
        const uint32_t sAl = stage + TILE_B;
        const uint32_t sWh = stage + 2 * TILE_B;

#pragma unroll
        for (int ks = 0; ks < 4; ks++) {
            const int acol = ks * 32 + acolh;
            uint32_t bh[8];
            {
                uint32_t boff = (uint32_t)((wn + browa) * TSTRIDE + ks * 32 + bcolh);
                ldsm4(bh,     sWh + boff);
                ldsm4(bh + 4, sWh + boff + 16 * TSTRIDE);
            }
#pragma unroll
            for (int mt = 0; mt < 4; mt++) {
                uint32_t ah[4], al[4];
                uint32_t off = (uint32_t)((wm + mt * 16 + arow) * TSTRIDE + acol);
                ldsm4(ah, sAh + off);
                ldsm4(al, sAl + off);
#pragma unroll
                for (int nt = 0; nt < 4; nt++) {
                    mma16816h(acc[mt][nt], ah, bh + nt * 2);
                    mma16816h(acc[mt][nt], al, bh + nt * 2);
                }
            }
        }
        __syncthreads();
    }

    const int r0 = lane >> 2;
    const int c0 = (lane & 3) * 2;
#pragma unroll
    for (int mt = 0; mt < 4; mt++) {
#pragma unroll
        for (int nt = 0; nt < 4; nt++) {
            int gm = m0 + wm + mt * 16 + r0;
            int gn = n0 + wn + nt * 8 + c0;
            float2 bv = *(const float2*)(bias + gn);
            float2 o0, o1;
            o0.x = acc[mt][nt][0] + bv.x;
            o0.y = acc[mt][nt][1] + bv.y;
            o1.x = acc[mt][nt][2] + bv.x;
            o1.y = acc[mt][nt][3] + bv.y;
            *(float2*)(C + (size_t)gm * DIM + gn) = o0;
            *(float2*)(C + (size_t)(gm + 8) * DIM + gn) = o1;
        }
    }
}

// ---------------- pack: rope + scale + per-head relayout (fp16 hi only) -----
__global__ void pack_qkv(const float* __restrict__ cosb,
                         const float* __restrict__ sinb)
{
    const int s = blockIdx.x;
    const int tid = threadIdx.x;
    const float scale = 0.11180339887498949f;

    for (int p = tid; p < NH * 20; p += 256) {
        int h = p / 20, dp = (p % 20) * 2;
        float2 c2 = *(const float2*)(cosb + s * HD + dp);
        float2 s2 = *(const float2*)(sinb + s * HD + dp);
        size_t ib = (size_t)s * DIM + h * HD + dp;
        size_t ob = ((size_t)h * S + s) * HD + dp;

        float2 qa = *(const float2*)(g_q + ib);
        float2 qb = *(const float2*)(g_q + ib + 40);
        *(uint32_t*)(g_qh + ob) = pkh((qa.x * c2.x - qb.x * s2.x) * scale,
                                      (qa.y * c2.y - qb.y * s2.y) * scale);
        *(uint32_t*)(g_qh + ob + 40) = pkh((qb.x * c2.x + qa.x * s2.x) * scale,
                                           (qb.y * c2.y + qa.y * s2.y) * scale);

        float2 ka = *(const float2*)(g_k + ib);
        float2 kb = *(const float2*)(g_k + ib + 40);
        *(uint32_t*)(g_kh + ob)      = pkh(ka.x * c2.x - kb.x * s2.x,
                                           ka.y * c2.y - kb.y * s2.y);
        *(uint32_t*)(g_kh + ob + 40) = pkh(kb.x * c2.x + ka.x * s2.x,
                                           kb.y * c2.y + ka.y * s2.y);
    }

    for (int p = tid; p < DIM / 2; p += 256) {
        int e = p * 2;
        int h = e / HD, d = e % HD;
        float2 v2 = *(const float2*)(g_v + (size_t)s * DIM + e);
        size_t ob = ((size_t)h * S + s) * HD + d;
        *(uint32_t*)(g_vh + ob) = pkh(v2.x, v2.y);
    }
}

// ---------------- flash attention: pure fp16 operands, fp32 softmax ---------
// Tiles: Q, K0, V0, K1, V1 (each 64 x 160B, stride 176)
#define ATS 176
#define ATB (64 * ATS)               // 11264
#define AQ  0
#define AK0 ATB
#define AV0 (2 * ATB)
#define AK1 (3 * ATB)
#define AV1 (4 * ATB)
#define APMAX (5 * ATB)
#define APLS  (APMAX + 512)
#define ATTN_SMEM (APLS + 256)       // 57088 B

__global__ __launch_bounds__(256, 2) void attn_mma(__half* __restrict__ ch,
                                                   __half* __restrict__ cl)
{
    extern __shared__ char sm[];
    const uint32_t sb = smem_u32(sm);
    const int tid = threadIdx.x;
    const int wid = tid >> 5;
    const int lane = tid & 31;

    const int qt = blockIdx.x;
    const int h  = blockIdx.y;
    const int sg = blockIdx.z;
    const int s0 = sg * SEG;
    const int q0 = s0 + qt * 64;
    const size_t hb = (size_t)h * S * HD;

    const int wm = (wid & 3) * 16;
    const int wh = wid >> 2;
    const int wn = wh * 32;

    float* pmax = (float*)(sm + APMAX);
    float* plsum = (float*)(sm + APLS);

    const char* qhp = (const char*)(g_qh + hb + (size_t)q0 * HD);
    const char* khp = (const char*)(g_kh + hb + (size_t)s0 * HD);
    const char* vhp = (const char*)(g_vh + hb + (size_t)s0 * HD);

    // single-tile loader (640 cp16)
    auto cp_tile = [&](uint32_t dst, const char* src, int rb) {
#pragma unroll
        for (int i = 0; i < 3; i++) {
            int f = i * 256 + tid;
            if (f < 640) {
                int r = f / 10, c = f - r * 10;
                CP_ASYNC16(sb + dst + r * ATS + c * 16,
                           src + (size_t)(rb + r) * 160 + c * 16);
            }
        }
    };

    cp_tile(AQ, qhp, 0);
    cp_tile(AK0, khp, 0);
    CP_COMMIT();                       // group: Q + K0
    cp_tile(AV0, vhp, 0);
    CP_COMMIT();                       // V0
    cp_tile(AK1, khp, 64);
    CP_COMMIT();                       // K1
    cp_tile(AV1, vhp, 64);
    CP_COMMIT();                       // V1

    float acc[10][4];
#pragma unroll
    for (int nt = 0; nt < 10; nt++)
#pragma unroll
        for (int i = 0; i < 4; i++) acc[nt][i] = 0.f;

    float mold0 = -1e30f, mold1 = -1e30f;
    float lsum0 = 0.f, lsum1 = 0.f;

    const int qrow = wm + (lane & 15);
    const uint32_t qcoloff = (uint32_t)((lane >> 4) * 16);
    const int krowa = wn + ((lane >> 4) << 3) + (lane & 7);
    const uint32_t kcoloff = (uint32_t)(((lane >> 3) & 1) * 16);
    const int r4 = lane >> 2;
    const int q2 = (lane & 3) * 2;

    for (int c = 0; c < 8; c++) {
        const uint32_t sKH = sb + ((c & 1) ? AK1 : AK0);
        const uint32_t sVH = sb + ((c & 1) ? AV1 : AV0);

        if (c == 7) { CP_WAIT1(); } else { CP_WAIT3(); }
        __syncthreads();

        // ---- S = Q K^T (fp16) ----
        float sa[4][4];
#pragma unroll
        for (int nt = 0; nt < 4; nt++)
#pragma unroll
            for (int i = 0; i < 4; i++) sa[nt][i] = 0.f;

#pragma unroll
        for (int ks = 0; ks < 5; ks++) {
            uint32_t qh4[4], kh[8];
            uint32_t qoff = (uint32_t)(qrow * ATS + ks * 32) + qcoloff;
            ldsm4(qh4, sb + AQ + qoff);
            uint32_t koff0 = (uint32_t)(krowa * ATS + ks * 32) + kcoloff;
            ldsm4(kh,     sKH + koff0);
            ldsm4(kh + 4, sKH + koff0 + 16 * ATS);
#pragma unroll
            for (int nt = 0; nt < 4; nt++)
                mma16816h(sa[nt], qh4, kh + nt * 2);
        }

        float mx0 = fmaxf(fmaxf(sa[0][0], sa[0][1]), fmaxf(sa[1][0], sa[1][1]));
        mx0 = fmaxf(mx0, fmaxf(fmaxf(sa[2][0], sa[2][1]), fmaxf(sa[3][0], sa[3][1])));
        float mx1 = fmaxf(fmaxf(sa[0][2], sa[0][3]), fmaxf(sa[1][2], sa[1][3]));
        mx1 = fmaxf(mx1, fmaxf(fmaxf(sa[2][2], sa[2][3]), fmaxf(sa[3][2], sa[3][3])));
        mx0 = fmaxf(mx0, __shfl_xor_sync(0xffffffffu, mx0, 1));
        mx0 = fmaxf(mx0, __shfl_xor_sync(0xffffffffu, mx0, 2));
        mx1 = fmaxf(mx1, __shfl_xor_sync(0xffffffffu, mx1, 1));
        mx1 = fmaxf(mx1, __shfl_xor_sync(0xffffffffu, mx1, 2));
        if ((lane & 3) == 0) {
            pmax[wh * 64 + wm + r4] = mx0;
            pmax[wh * 64 + wm + 8 + r4] = mx1;
        }

        if (c == 7) { CP_WAIT0(); } else { CP_WAIT2(); }
        __syncthreads();

        float ma0 = fmaxf(pmax[wm + r4], pmax[64 + wm + r4]);
        float ma1 = fmaxf(pmax[wm + 8 + r4], pmax[64 + wm + 8 + r4]);
        float mn0 = fmaxf(mold0, ma0);
        float mn1 = fmaxf(mold1, ma1);
        float fs0 = __expf(mold0 - mn0);
        float fs1 = __expf(mold1 - mn1);
        mold0 = mn0; mold1 = mn1;

        float s0r = 0.f, s1r = 0.f;
#pragma unroll
        for (int nt = 0; nt < 4; nt++) {
            sa[nt][0] = __expf(sa[nt][0] - mn0);
            sa[nt][1] = __expf(sa[nt][1] - mn0);
            sa[nt][2] = __expf(sa[nt][2] - mn1);
            sa[nt][3] = __expf(sa[nt][3] - mn1);
            s0r += sa[nt][0] + sa[nt][1];
            s1r += sa[nt][2] + sa[nt][3];
        }
        s0r += __shfl_xor_sync(0xffffffffu, s0r, 1);
        s0r += __shfl_xor_sync(0xffffffffu, s0r, 2);
        s1r += __shfl_xor_sync(0xffffffffu, s1r, 1);
        s1r += __shfl_xor_sync(0xffffffffu, s1r, 2);
        lsum0 = lsum0 * fs0 + s0r;
        lsum1 = lsum1 * fs1 + s1r;

#pragma unroll
        for (int nt = 0; nt < 10; nt++) {
            acc[nt][0] *= fs0; acc[nt][1] *= fs0;
            acc[nt][2] *= fs1; acc[nt][3] *= fs1;
        }

        // ---- PV over this warp's k-half (p fp16, v fp16) ----
#pragma unroll
        for (int kb = 0; kb < 2; kb++) {
            uint32_t aH[4];
            aH[0] = pkh(sa[2 * kb][0], sa[2 * kb][1]);
            aH[1] = pkh(sa[2 * kb][2], sa[2 * kb][3]);
            aH[2] = pkh(sa[2 * kb + 1][0], sa[2 * kb + 1][1]);
            aH[3] = pkh(sa[2 * kb + 1][2], sa[2 * kb + 1][3]);
            const int vrow = wn + kb * 16 + (lane & 15);
#pragma unroll
            for (int np = 0; np < 5; np++) {
                uint32_t vh4[4];
                uint32_t voff = (uint32_t)(vrow * ATS + (np * 16 + ((lane >> 4) << 3)) * 2);
                ldsm4t(vh4, sVH + voff);
                mma16816h(acc[np * 2], aH, vh4);
                mma16816h(acc[np * 2 + 1], aH, vh4 + 2);
            }
        }
        __syncthreads();

        if (c + 2 < 8) {
            cp_tile((c & 1) ? AK1 : AK0, khp, (c + 2) * 64);
            CP_COMMIT();
            cp_tile((c & 1) ? AV1 : AV0, vhp, (c + 2) * 64);
            CP_COMMIT();
        }
    }

    // ---- epilogue: combine column halves, normalize, write ctx hi/lo -------
    float* cb = (float*)(sm + AK0);
    if (wh == 1) {
#pragma unroll
        for (int nt = 0; nt < 10; nt++) {
            int cc = nt * 8 + q2;
            cb[(wm + r4) * 80 + cc]     = acc[nt][0];
            cb[(wm + r4) * 80 + cc + 1] = acc[nt][1];
            cb[(wm + r4 + 8) * 80 + cc]     = acc[nt][2];
            cb[(wm + r4 + 8) * 80 + cc + 1] = acc[nt][3];
        }
        if ((lane & 3) == 0) {
            plsum[wm + r4] = lsum0;
            plsum[wm + r4 + 8] = lsum1;
        }
    }
    __syncthreads();
    if (wh == 0) {
        float li0 = 1.f / (lsum0 + plsum[wm + r4]);
        float li1 = 1.f / (lsum1 + plsum[wm + r4 + 8]);
        int gr0 = q0 + wm + r4;
#pragma unroll
        for (int nt = 0; nt < 10; nt++) {
            int col = h * HD + nt * 8 + q2;
            float x0 = (acc[nt][0] + cb[(wm + r4) * 80 + nt * 8 + q2]) * li0;
            float y0 = (acc[nt][1] + cb[(wm + r4) * 80 + nt * 8 + q2 + 1]) * li0;
            float x1 = (acc[nt][2] + cb[(wm + r4 + 8) * 80 + nt * 8 + q2]) * li1;
            float y1 = (acc[nt][3] + cb[(wm + r4 + 8) * 80 + nt * 8 + q2 + 1]) * li1;
            size_t a0 = (size_t)gr0 * DIM + col;
            size_t a1 = a0 + (size_t)8 * DIM;
            uint32_t lo;
            uint32_t hi = pk2h(x0, y0, lo);
            *(uint32_t*)(ch + a0) = hi;
            *(uint32_t*)(cl + a0) = lo;
            hi = pk2h(x1, y1, lo);
            *(uint32_t*)(ch + a1) = hi;
            *(uint32_t*)(cl + a1) = lo;
        }
    }
}

// ---------------------------------------------------------------------------
extern "C" void kernel_launch(void* const* d_in, const int* in_sizes, int n_in,
                              void* d_out, int out_size)
{
    const float* hs   = (const float*)d_in[0];
    const float* cosb = (const float*)d_in[1];
    const float* sinb = (const float*)d_in[2];
    const float* wq   = (const float*)d_in[3];
    const float* bq   = (const float*)d_in[4];
    const float* wk   = (const float*)d_in[5];
    const float* bk   = (const float*)d_in[6];
    const float* wv   = (const float*)d_in[7];
    const float* bv   = (const float*)d_in[8];
    const float* wo   = (const float*)d_in[9];
    const float* bo   = (const float*)d_in[10];
    float* out = (float*)d_out;

    float *qp, *kp, *vp;
    cudaGetSymbolAddress((void**)&qp, g_q);
    cudaGetSymbolAddress((void**)&kp, g_k);
    cudaGetSymbolAddress((void**)&vp, g_v);
    __half *ah, *al, *wh, *ch, *cl;
    cudaGetSymbolAddress((void**)&ah, g_ah);
    cudaGetSymbolAddress((void**)&al, g_al);
    cudaGetSymbolAddress((void**)&wh, g_wh);
    cudaGetSymbolAddress((void**)&ch, g_ch);
    cudaGetSymbolAddress((void**)&cl, g_cl);

    cudaFuncSetAttribute(gemm_hmma,
                         cudaFuncAttributeMaxDynamicSharedMemorySize, GEMM_SMEM);
    cudaFuncSetAttribute(attn_mma,
                         cudaFuncAttributeMaxDynamicSharedMemorySize, ATTN_SMEM);

    split_hs<<<(S * DIM / 4) / 256, 256>>>((const float4*)hs, (uint2*)ah, (uint2*)al,
                                           S * DIM / 4);
    split_w4<<<dim3((DIM * DIM / 4) / 256, 4), 256>>>(
        (const float4*)wq, (const float4*)wk, (const float4*)wv, (const float4*)wo,
        (uint2*)wh);

    gemm_hmma<<<dim3(DIM / GBN, S / GBM, 3), 256, GEMM_SMEM>>>(
        ah, al, wh, 0, bq, bk, bv, qp, kp, vp);

    pack_qkv<<<S, 256>>>(cosb, sinb);

    attn_mma<<<dim3(8, NH, NSEG), 256, ATTN_SMEM>>>(ch, cl);

    gemm_hmma<<<dim3(DIM / GBN, S / GBM, 1), 256, GEMM_SMEM>>>(
        ch, cl, wh, 3, bo, bo, bo, out, out, out);
}

// round 15
// speedup vs baseline: 2.2361x; 1.4493x over previous
#include <cuda_runtime.h>
#include <cuda_bf16.h>
#include <cuda_fp16.h>
#include <cstdint>
#include <math.h>

#define S    3072
#define DIM  1280
#define NH   16
#define HD   80
#define SEG  512
#define NSEG 6

// ---------------- scratch (__device__ globals; no allocs allowed) ----------
__device__ float g_q[S * DIM];
__device__ float g_k[S * DIM];
__device__ float g_v[S * DIM];

__device__ __half g_ah[S * DIM];              // hidden (fp16)
__device__ __half g_wh[4 * DIM * DIM];        // weights (fp16)
__device__ __half g_ch[S * DIM];              // ctx (fp16)

// attention operands (fp16)
__device__ __half g_qh[NH * S * HD];
__device__ __half g_kh[NH * S * HD];
__device__ __half g_vh[NH * S * HD];

// ---------------- PTX helpers (sm_80-era, arch-neutral) --------------------
__device__ __forceinline__ uint32_t smem_u32(const void* p) {
    uint32_t a;
    asm("{ .reg .u64 t; cvta.to.shared.u64 t, %1; cvt.u32.u64 %0, t; }"
        : "=r"(a) : "l"(p));
    return a;
}
__device__ __forceinline__ void ldsm4(uint32_t* r, uint32_t addr) {
    asm volatile("ldmatrix.sync.aligned.m8n8.x4.shared.b16 {%0,%1,%2,%3}, [%4];"
                 : "=r"(r[0]), "=r"(r[1]), "=r"(r[2]), "=r"(r[3]) : "r"(addr));
}
__device__ __forceinline__ void ldsm4t(uint32_t* r, uint32_t addr) {
    asm volatile("ldmatrix.sync.aligned.m8n8.x4.trans.shared.b16 {%0,%1,%2,%3}, [%4];"
                 : "=r"(r[0]), "=r"(r[1]), "=r"(r[2]), "=r"(r[3]) : "r"(addr));
}
__device__ __forceinline__ void mma16816h(float* d, const uint32_t* a, const uint32_t* b) {
    asm volatile(
        "mma.sync.aligned.m16n8k16.row.col.f32.f16.f16.f32 "
        "{%0,%1,%2,%3}, {%4,%5,%6,%7}, {%8,%9}, {%0,%1,%2,%3};"
        : "+f"(d[0]), "+f"(d[1]), "+f"(d[2]), "+f"(d[3])
        : "r"(a[0]), "r"(a[1]), "r"(a[2]), "r"(a[3]), "r"(b[0]), "r"(b[1]));
}

#define CP_ASYNC16(dst, src) \
    asm volatile("cp.async.cg.shared.global [%0], [%1], 16;" :: "r"(dst), "l"(src))
#define CP_COMMIT() asm volatile("cp.async.commit_group;")
#define CP_WAIT3()  asm volatile("cp.async.wait_group 3;")
#define CP_WAIT2()  asm volatile("cp.async.wait_group 2;")
#define CP_WAIT1()  asm volatile("cp.async.wait_group 1;")
#define CP_WAIT0()  asm volatile("cp.async.wait_group 0;")

__device__ __forceinline__ uint32_t pkh(float x, float y) {
    __half2 H = __halves2half2(__float2half_rn(x), __float2half_rn(y));
    return *(uint32_t*)&H;
}

// ---------------- fp32 -> fp16 conversions -----------------------------------
__global__ void split_hs(const float4* __restrict__ src,
                         uint2* __restrict__ hi, int n4) {
    int i = blockIdx.x * blockDim.x + threadIdx.x;
    if (i < n4) {
        float4 v = src[i];
        hi[i] = make_uint2(pkh(v.x, v.y), pkh(v.z, v.w));
    }
}

__global__ void split_w4(const float4* __restrict__ s0, const float4* __restrict__ s1,
                         const float4* __restrict__ s2, const float4* __restrict__ s3,
                         uint2* __restrict__ hi) {
    int z = blockIdx.y;
    const float4* s = (z == 0) ? s0 : (z == 1) ? s1 : (z == 2) ? s2 : s3;
    size_t base = (size_t)z * (DIM * DIM / 4);
    int i = blockIdx.x * blockDim.x + threadIdx.x;
    float4 v = s[i];
    hi[base + i] = make_uint2(pkh(v.x, v.y), pkh(v.z, v.w));
}

// ---------------- HMMA fp16 GEMM, BK=64 --------------------------------------
// C = A@W^T + bias.  A fp16, W fp16, fp32 accum.
#define GBM 128
#define GBN 128
#define NCHUNK (DIM / 64)            // 20
#define TSTRIDE 144                  // 128B row + 16B pad
#define TILE_B  (128 * TSTRIDE)      // 18432
#define STAGE_B (2 * TILE_B)         // 36864 (A, W)
#define GEMM_SMEM (2 * STAGE_B)      // 73728

__global__ __launch_bounds__(256, 2) void gemm_hmma(
    const __half* __restrict__ Ahi,
    const __half* __restrict__ Wh_base,
    int zoff,
    const float* __restrict__ bias0, const float* __restrict__ bias1, const float* __restrict__ bias2,
    float* __restrict__ C0, float* __restrict__ C1, float* __restrict__ C2)
{
    extern __shared__ char smem[];
    const uint32_t sb = smem_u32(smem);
    const int tid  = threadIdx.x;
    const int wid  = tid >> 5;
    const int lane = tid & 31;

    const int z = blockIdx.z;
    const __half* Wh = Wh_base + (size_t)(zoff + z) * DIM * DIM;
    const float* bias = (z == 0) ? bias0 : (z == 1) ? bias1 : bias2;
    float* C = (z == 0) ? C0 : (z == 1) ? C1 : C2;

    const int m0 = blockIdx.y * GBM;
    const int n0 = blockIdx.x * GBN;
    const int wm = (wid & 1) * 64;
    const int wn = (wid >> 1) * 32;

    const char* srcs[2];
    srcs[0] = (const char*)(Ahi + (size_t)m0 * DIM);
    srcs[1] = (const char*)(Wh  + (size_t)n0 * DIM);

    float acc[4][4][4];
#pragma unroll
    for (int mt = 0; mt < 4; mt++)
#pragma unroll
        for (int nt = 0; nt < 4; nt++)
#pragma unroll
            for (int i = 0; i < 4; i++) acc[mt][nt][i] = 0.f;

    // load chunk 0 into buffer 0 (2 tiles x 128 rows x 128B = 8 cp16/thread)
    {
#pragma unroll
        for (int i = 0; i < 8; i++) {
            int t = i >> 2;
            int e = (i & 3) * 256 + tid;     // 0..1023
            int row = e >> 3, c16 = e & 7;
            CP_ASYNC16(sb + t * TILE_B + row * TSTRIDE + c16 * 16,
                       srcs[t] + (size_t)row * (DIM * 2) + c16 * 16);
        }
        CP_COMMIT();
    }

    const int arow = lane & 15;
    const int acolh = (lane >> 4) * 16;
    const int browa = ((lane >> 4) << 3) + (lane & 7);
    const int bcolh = ((lane >> 3) & 1) * 16;

    for (int c = 0; c < NCHUNK; c++) {
        if (c + 1 < NCHUNK) {
            const int k0b = (c + 1) * 128;
            uint32_t d = sb + ((c + 1) & 1) * STAGE_B;
#pragma unroll
            for (int i = 0; i < 8; i++) {
                int t = i >> 2;
                int e = (i & 3) * 256 + tid;
                int row = e >> 3, c16 = e & 7;
                CP_ASYNC16(d + t * TILE_B + row * TSTRIDE + c16 * 16,
                           srcs[t] + (size_t)row * (DIM * 2) + k0b + c16 * 16);
            }
            CP_COMMIT();
            CP_WAIT1();
        } else {
            CP_WAIT0();
        }
        __syncthreads();

        const uint32_t stage = sb + (c & 1) * STAGE_B;
        const uint32_t sA = stage;
        const uint32_t sW = stage + TILE_B;

#pragma unroll
        for (int ks = 0; ks < 4; ks++) {
            const int acol = ks * 32 + acolh;
            uint32_t bh[8];
            {
                uint32_t boff = (uint32_t)((wn + browa) * TSTRIDE + ks * 32 + bcolh);
                ldsm4(bh,     sW + boff);
                ldsm4(bh + 4, sW + boff + 16 * TSTRIDE);
            }
#pragma unroll
            for (int mt = 0; mt < 4; mt++) {
                uint32_t ah[4];
                uint32_t off = (uint32_t)((wm + mt * 16 + arow) * TSTRIDE + acol);
                ldsm4(ah, sA + off);
#pragma unroll
                for (int nt = 0; nt < 4; nt++)
                    mma16816h(acc[mt][nt], ah, bh + nt * 2);
            }
        }
        __syncthreads();
    }

    const int r0 = lane >> 2;
    const int c0 = (lane & 3) * 2;
#pragma unroll
    for (int mt = 0; mt < 4; mt++) {
#pragma unroll
        for (int nt = 0; nt < 4; nt++) {
            int gm = m0 + wm + mt * 16 + r0;
            int gn = n0 + wn + nt * 8 + c0;
            float2 bv = *(const float2*)(bias + gn);
            float2 o0, o1;
            o0.x = acc[mt][nt][0] + bv.x;
            o0.y = acc[mt][nt][1] + bv.y;
            o1.x = acc[mt][nt][2] + bv.x;
            o1.y = acc[mt][nt][3] + bv.y;
            *(float2*)(C + (size_t)gm * DIM + gn) = o0;
            *(float2*)(C + (size_t)(gm + 8) * DIM + gn) = o1;
        }
    }
}

// ---------------- pack: rope + scale + per-head relayout (fp16) -------------
__global__ void pack_qkv(const float* __restrict__ cosb,
                         const float* __restrict__ sinb)
{
    const int s = blockIdx.x;
    const int tid = threadIdx.x;
    const float scale = 0.11180339887498949f;

    for (int p = tid; p < NH * 20; p += 256) {
        int h = p / 20, dp = (p % 20) * 2;
        float2 c2 = *(const float2*)(cosb + s * HD + dp);
        float2 s2 = *(const float2*)(sinb + s * HD + dp);
        size_t ib = (size_t)s * DIM + h * HD + dp;
        size_t ob = ((size_t)h * S + s) * HD + dp;

        float2 qa = *(const float2*)(g_q + ib);
        float2 qb = *(const float2*)(g_q + ib + 40);
        *(uint32_t*)(g_qh + ob) = pkh((qa.x * c2.x - qb.x * s2.x) * scale,
                                      (qa.y * c2.y - qb.y * s2.y) * scale);
        *(uint32_t*)(g_qh + ob + 40) = pkh((qb.x * c2.x + qa.x * s2.x) * scale,
                                           (qb.y * c2.y + qa.y * s2.y) * scale);

        float2 ka = *(const float2*)(g_k + ib);
        float2 kb = *(const float2*)(g_k + ib + 40);
        *(uint32_t*)(g_kh + ob)      = pkh(ka.x * c2.x - kb.x * s2.x,
                                           ka.y * c2.y - kb.y * s2.y);
        *(uint32_t*)(g_kh + ob + 40) = pkh(kb.x * c2.x + ka.x * s2.x,
                                           kb.y * c2.y + ka.y * s2.y);
    }

    for (int p = tid; p < DIM / 2; p += 256) {
        int e = p * 2;
        int h = e / HD, d = e % HD;
        float2 v2 = *(const float2*)(g_v + (size_t)s * DIM + e);
        size_t ob = ((size_t)h * S + s) * HD + d;
        *(uint32_t*)(g_vh + ob) = pkh(v2.x, v2.y);
    }
}

// ---------------- flash attention: pure fp16 operands, fp32 softmax ---------
#define ATS 176
#define ATB (64 * ATS)               // 11264
#define AQ  0
#define AK0 ATB
#define AV0 (2 * ATB)
#define AK1 (3 * ATB)
#define AV1 (4 * ATB)
#define APMAX (5 * ATB)
#define APLS  (APMAX + 512)
#define ATTN_SMEM (APLS + 256)       // 57088 B

__global__ __launch_bounds__(256, 2) void attn_mma(__half* __restrict__ ch)
{
    extern __shared__ char sm[];
    const uint32_t sb = smem_u32(sm);
    const int tid = threadIdx.x;
    const int wid = tid >> 5;
    const int lane = tid & 31;

    const int qt = blockIdx.x;
    const int h  = blockIdx.y;
    const int sg = blockIdx.z;
    const int s0 = sg * SEG;
    const int q0 = s0 + qt * 64;
    const size_t hb = (size_t)h * S * HD;

    const int wm = (wid & 3) * 16;
    const int wh = wid >> 2;
    const int wn = wh * 32;

    float* pmax = (float*)(sm + APMAX);
    float* plsum = (float*)(sm + APLS);

    const char* qhp = (const char*)(g_qh + hb + (size_t)q0 * HD);
    const char* khp = (const char*)(g_kh + hb + (size_t)s0 * HD);
    const char* vhp = (const char*)(g_vh + hb + (size_t)s0 * HD);

    auto cp_tile = [&](uint32_t dst, const char* src, int rb) {
#pragma unroll
        for (int i = 0; i < 3; i++) {
            int f = i * 256 + tid;
            if (f < 640) {
                int r = f / 10, c = f - r * 10;
                CP_ASYNC16(sb + dst + r * ATS + c * 16,
                           src + (size_t)(rb + r) * 160 + c * 16);
            }
        }
    };

    cp_tile(AQ, qhp, 0);
    cp_tile(AK0, khp, 0);
    CP_COMMIT();
    cp_tile(AV0, vhp, 0);
    CP_COMMIT();
    cp_tile(AK1, khp, 64);
    CP_COMMIT();
    cp_tile(AV1, vhp, 64);
    CP_COMMIT();

    float acc[10][4];
#pragma unroll
    for (int nt = 0; nt < 10; nt++)
#pragma unroll
        for (int i = 0; i < 4; i++) acc[nt][i] = 0.f;

    float mold0 = -1e30f, mold1 = -1e30f;
    float lsum0 = 0.f, lsum1 = 0.f;

    const int qrow = wm + (lane & 15);
    const uint32_t qcoloff = (uint32_t)((lane >> 4) * 16);
    const int krowa = wn + ((lane >> 4) << 3) + (lane & 7);
    const uint32_t kcoloff = (uint32_t)(((lane >> 3) & 1) * 16);
    const int r4 = lane >> 2;
    const int q2 = (lane & 3) * 2;

    for (int c = 0; c < 8; c++) {
        const uint32_t sKH = sb + ((c & 1) ? AK1 : AK0);
        const uint32_t sVH = sb + ((c & 1) ? AV1 : AV0);

        if (c == 7) { CP_WAIT1(); } else { CP_WAIT3(); }
        __syncthreads();

        float sa[4][4];
#pragma unroll
        for (int nt = 0; nt < 4; nt++)
#pragma unroll
            for (int i = 0; i < 4; i++) sa[nt][i] = 0.f;

#pragma unroll
        for (int ks = 0; ks < 5; ks++) {
            uint32_t qh4[4], kh[8];
            uint32_t qoff = (uint32_t)(qrow * ATS + ks * 32) + qcoloff;
            ldsm4(qh4, sb + AQ + qoff);
            uint32_t koff0 = (uint32_t)(krowa * ATS + ks * 32) + kcoloff;
            ldsm4(kh,     sKH + koff0);
            ldsm4(kh + 4, sKH + koff0 + 16 * ATS);
#pragma unroll
            for (int nt = 0; nt < 4; nt++)
                mma16816h(sa[nt], qh4, kh + nt * 2);
        }

        float mx0 = fmaxf(fmaxf(sa[0][0], sa[0][1]), fmaxf(sa[1][0], sa[1][1]));
        mx0 = fmaxf(mx0, fmaxf(fmaxf(sa[2][0], sa[2][1]), fmaxf(sa[3][0], sa[3][1])));
        float mx1 = fmaxf(fmaxf(sa[0][2], sa[0][3]), fmaxf(sa[1][2], sa[1][3]));
        mx1 = fmaxf(mx1, fmaxf(fmaxf(sa[2][2], sa[2][3]), fmaxf(sa[3][2], sa[3][3])));
        mx0 = fmaxf(mx0, __shfl_xor_sync(0xffffffffu, mx0, 1));
        mx0 = fmaxf(mx0, __shfl_xor_sync(0xffffffffu, mx0, 2));
        mx1 = fmaxf(mx1, __shfl_xor_sync(0xffffffffu, mx1, 1));
        mx1 = fmaxf(mx1, __shfl_xor_sync(0xffffffffu, mx1, 2));
        if ((lane & 3) == 0) {
            pmax[wh * 64 + wm + r4] = mx0;
            pmax[wh * 64 + wm + 8 + r4] = mx1;
        }

        if (c == 7) { CP_WAIT0(); } else { CP_WAIT2(); }
        __syncthreads();

        float ma0 = fmaxf(pmax[wm + r4], pmax[64 + wm + r4]);
        float ma1 = fmaxf(pmax[wm + 8 + r4], pmax[64 + wm + 8 + r4]);
        float mn0 = fmaxf(mold0, ma0);
        float mn1 = fmaxf(mold1, ma1);
        float fs0 = __expf(mold0 - mn0);
        float fs1 = __expf(mold1 - mn1);
        mold0 = mn0; mold1 = mn1;

        float s0r = 0.f, s1r = 0.f;
#pragma unroll
        for (int nt = 0; nt < 4; nt++) {
            sa[nt][0] = __expf(sa[nt][0] - mn0);
            sa[nt][1] = __expf(sa[nt][1] - mn0);
            sa[nt][2] = __expf(sa[nt][2] - mn1);
            sa[nt][3] = __expf(sa[nt][3] - mn1);
            s0r += sa[nt][0] + sa[nt][1];
            s1r += sa[nt][2] + sa[nt][3];
        }
        s0r += __shfl_xor_sync(0xffffffffu, s0r, 1);
        s0r += __shfl_xor_sync(0xffffffffu, s0r, 2);
        s1r += __shfl_xor_sync(0xffffffffu, s1r, 1);
        s1r += __shfl_xor_sync(0xffffffffu, s1r, 2);
        lsum0 = lsum0 * fs0 + s0r;
        lsum1 = lsum1 * fs1 + s1r;

#pragma unroll
        for (int nt = 0; nt < 10; nt++) {
            acc[nt][0] *= fs0; acc[nt][1] *= fs0;
            acc[nt][2] *= fs1; acc[nt][3] *= fs1;
        }

#pragma unroll
        for (int kb = 0; kb < 2; kb++) {
            uint32_t aH[4];
            aH[0] = pkh(sa[2 * kb][0], sa[2 * kb][1]);
            aH[1] = pkh(sa[2 * kb][2], sa[2 * kb][3]);
            aH[2] = pkh(sa[2 * kb + 1][0], sa[2 * kb + 1][1]);
            aH[3] = pkh(sa[2 * kb + 1][2], sa[2 * kb + 1][3]);
            const int vrow = wn + kb * 16 + (lane & 15);
#pragma unroll
            for (int np = 0; np < 5; np++) {
                uint32_t vh4[4];
                uint32_t voff = (uint32_t)(vrow * ATS + (np * 16 + ((lane >> 4) << 3)) * 2);
                ldsm4t(vh4, sVH + voff);
                mma16816h(acc[np * 2], aH, vh4);
                mma16816h(acc[np * 2 + 1], aH, vh4 + 2);
            }
        }
        __syncthreads();

        if (c + 2 < 8) {
            cp_tile((c & 1) ? AK1 : AK0, khp, (c + 2) * 64);
            CP_COMMIT();
            cp_tile((c & 1) ? AV1 : AV0, vhp, (c + 2) * 64);
            CP_COMMIT();
        }
    }

    // ---- epilogue: combine column halves, normalize, write ctx fp16 --------
    float* cb = (float*)(sm + AK0);
    if (wh == 1) {
#pragma unroll
        for (int nt = 0; nt < 10; nt++) {
            int cc = nt * 8 + q2;
            cb[(wm + r4) * 80 + cc]     = acc[nt][0];
            cb[(wm + r4) * 80 + cc + 1] = acc[nt][1];
            cb[(wm + r4 + 8) * 80 + cc]     = acc[nt][2];
            cb[(wm + r4 + 8) * 80 + cc + 1] = acc[nt][3];
        }
        if ((lane & 3) == 0) {
            plsum[wm + r4] = lsum0;
            plsum[wm + r4 + 8] = lsum1;
        }
    }
    __syncthreads();
    if (wh == 0) {
        float li0 = 1.f / (lsum0 + plsum[wm + r4]);
        float li1 = 1.f / (lsum1 + plsum[wm + r4 + 8]);
        int gr0 = q0 + wm + r4;
#pragma unroll
        for (int nt = 0; nt < 10; nt++) {
            int col = h * HD + nt * 8 + q2;
            float x0 = (acc[nt][0] + cb[(wm + r4) * 80 + nt * 8 + q2]) * li0;
            float y0 = (acc[nt][1] + cb[(wm + r4) * 80 + nt * 8 + q2 + 1]) * li0;
            float x1 = (acc[nt][2] + cb[(wm + r4 + 8) * 80 + nt * 8 + q2]) * li1;
            float y1 = (acc[nt][3] + cb[(wm + r4 + 8) * 80 + nt * 8 + q2 + 1]) * li1;
            size_t a0 = (size_t)gr0 * DIM + col;
            size_t a1 = a0 + (size_t)8 * DIM;
            *(uint32_t*)(ch + a0) = pkh(x0, y0);
            *(uint32_t*)(ch + a1) = pkh(x1, y1);
        }
    }
}

// ---------------------------------------------------------------------------
extern "C" void kernel_launch(void* const* d_in, const int* in_sizes, int n_in,
                              void* d_out, int out_size)
{
    const float* hs   = (const float*)d_in[0];
    const float* cosb = (const float*)d_in[1];
    const float* sinb = (const float*)d_in[2];
    const float* wq   = (const float*)d_in[3];
    const float* bq   = (const float*)d_in[4];
    const float* wk   = (const float*)d_in[5];
    const float* bk   = (const float*)d_in[6];
    const float* wv   = (const float*)d_in[7];
    const float* bv   = (const float*)d_in[8];
    const float* wo   = (const float*)d_in[9];
    const float* bo   = (const float*)d_in[10];
    float* out = (float*)d_out;

    float *qp, *kp, *vp;
    cudaGetSymbolAddress((void**)&qp, g_q);
    cudaGetSymbolAddress((void**)&kp, g_k);
    cudaGetSymbolAddress((void**)&vp, g_v);
    __half *ah, *wh, *ch;
    cudaGetSymbolAddress((void**)&ah, g_ah);
    cudaGetSymbolAddress((void**)&wh, g_wh);
    cudaGetSymbolAddress((void**)&ch, g_ch);

    cudaFuncSetAttribute(gemm_hmma,
                         cudaFuncAttributeMaxDynamicSharedMemorySize, GEMM_SMEM);
    cudaFuncSetAttribute(attn_mma,
                         cudaFuncAttributeMaxDynamicSharedMemorySize, ATTN_SMEM);

    split_hs<<<(S * DIM / 4) / 256, 256>>>((const float4*)hs, (uint2*)ah, S * DIM / 4);
    split_w4<<<dim3((DIM * DIM / 4) / 256, 4), 256>>>(
        (const float4*)wq, (const float4*)wk, (const float4*)wv, (const float4*)wo,
        (uint2*)wh);

    gemm_hmma<<<dim3(DIM / GBN, S / GBM, 3), 256, GEMM_SMEM>>>(
        ah, wh, 0, bq, bk, bv, qp, kp, vp);

    pack_qkv<<<S, 256>>>(cosb, sinb);

    attn_mma<<<dim3(8, NH, NSEG), 256, ATTN_SMEM>>>(ch);

    gemm_hmma<<<dim3(DIM / GBN, S / GBM, 1), 256, GEMM_SMEM>>>(
        ch, wh, 3, bo, bo, bo, out, out, out);
}

// round 16
// speedup vs baseline: 2.3281x; 1.0411x over previous
#include <cuda_runtime.h>
#include <cuda_bf16.h>
#include <cuda_fp16.h>
#include <cstdint>
#include <math.h>

#define S    3072
#define DIM  1280
#define NH   16
#define HD   80
#define SEG  512
#define NSEG 6

// ---------------- scratch (__device__ globals; no allocs allowed) ----------
__device__ float g_q[S * DIM];
__device__ float g_k[S * DIM];

__device__ __half g_ah[S * DIM];              // hidden (fp16)
__device__ __half g_wh[4 * DIM * DIM];        // weights (fp16)
__device__ __half g_ch[S * DIM];              // ctx (fp16)

// attention operands (fp16)
__device__ __half g_qh[NH * S * HD];
__device__ __half g_kh[NH * S * HD];
__device__ __half g_vh[NH * S * HD];

// ---------------- PTX helpers (sm_80-era, arch-neutral) --------------------
__device__ __forceinline__ uint32_t smem_u32(const void* p) {
    uint32_t a;
    asm("{ .reg .u64 t; cvta.to.shared.u64 t, %1; cvt.u32.u64 %0, t; }"
        : "=r"(a) : "l"(p));
    return a;
}
__device__ __forceinline__ void ldsm4(uint32_t* r, uint32_t addr) {
    asm volatile("ldmatrix.sync.aligned.m8n8.x4.shared.b16 {%0,%1,%2,%3}, [%4];"
                 : "=r"(r[0]), "=r"(r[1]), "=r"(r[2]), "=r"(r[3]) : "r"(addr));
}
__device__ __forceinline__ void ldsm4t(uint32_t* r, uint32_t addr) {
    asm volatile("ldmatrix.sync.aligned.m8n8.x4.trans.shared.b16 {%0,%1,%2,%3}, [%4];"
                 : "=r"(r[0]), "=r"(r[1]), "=r"(r[2]), "=r"(r[3]) : "r"(addr));
}
__device__ __forceinline__ void mma16816h(float* d, const uint32_t* a, const uint32_t* b) {
    asm volatile(
        "mma.sync.aligned.m16n8k16.row.col.f32.f16.f16.f32 "
        "{%0,%1,%2,%3}, {%4,%5,%6,%7}, {%8,%9}, {%0,%1,%2,%3};"
        : "+f"(d[0]), "+f"(d[1]), "+f"(d[2]), "+f"(d[3])
        : "r"(a[0]), "r"(a[1]), "r"(a[2]), "r"(a[3]), "r"(b[0]), "r"(b[1]));
}

#define CP_ASYNC16(dst, src) \
    asm volatile("cp.async.cg.shared.global [%0], [%1], 16;" :: "r"(dst), "l"(src))
#define CP_COMMIT() asm volatile("cp.async.commit_group;")
#define CP_WAIT1()  asm volatile("cp.async.wait_group 1;")
#define CP_WAIT0()  asm volatile("cp.async.wait_group 0;")

__device__ __forceinline__ uint32_t pkh(float x, float y) {
    __half2 H = __halves2half2(__float2half_rn(x), __float2half_rn(y));
    return *(uint32_t*)&H;
}

// ---------------- fp32 -> fp16 conversion (one launch) ----------------------
#define HS4 (S * DIM / 4)
#define W4  (DIM * DIM / 4)
__global__ void split_all(const float4* __restrict__ hs,
                          const float4* __restrict__ w0, const float4* __restrict__ w1,
                          const float4* __restrict__ w2, const float4* __restrict__ w3,
                          uint2* __restrict__ ah, uint2* __restrict__ wh) {
    int i = blockIdx.x * blockDim.x + threadIdx.x;
    if (i < HS4) {
        float4 v = hs[i];
        ah[i] = make_uint2(pkh(v.x, v.y), pkh(v.z, v.w));
    } else {
        int j = i - HS4;
        int z = j / W4, r = j - z * W4;
        const float4* s = (z == 0) ? w0 : (z == 1) ? w1 : (z == 2) ? w2 : w3;
        float4 v = s[r];
        wh[(size_t)z * W4 + r] = make_uint2(pkh(v.x, v.y), pkh(v.z, v.w));
    }
}

// ---------------- HMMA fp16 GEMM, BK=64 --------------------------------------
#define GBM 128
#define GBN 128
#define NCHUNK (DIM / 64)            // 20
#define TSTRIDE 144
#define TILE_B  (128 * TSTRIDE)
#define STAGE_B (2 * TILE_B)
#define GEMM_SMEM (2 * STAGE_B)      // 73728

__global__ __launch_bounds__(256, 2) void gemm_hmma(
    const __half* __restrict__ Ahi,
    const __half* __restrict__ Wh_base,
    int zoff,
    const float* __restrict__ bias0, const float* __restrict__ bias1, const float* __restrict__ bias2,
    float* __restrict__ C0, float* __restrict__ C1,
    __half* __restrict__ Vout)       // non-null: z==2 writes per-head fp16 V
{
    extern __shared__ char smem[];
    const uint32_t sb = smem_u32(smem);
    const int tid  = threadIdx.x;
    const int wid  = tid >> 5;
    const int lane = tid & 31;

    const int z = blockIdx.z;
    const __half* Wh = Wh_base + (size_t)(zoff + z) * DIM * DIM;
    const float* bias = (z == 0) ? bias0 : (z == 1) ? bias1 : bias2;
    float* C = (z == 0) ? C0 : C1;

    const int m0 = blockIdx.y * GBM;
    const int n0 = blockIdx.x * GBN;
    const int wm = (wid & 1) * 64;
    const int wn = (wid >> 1) * 32;

    const char* srcs[2];
    srcs[0] = (const char*)(Ahi + (size_t)m0 * DIM);
    srcs[1] = (const char*)(Wh  + (size_t)n0 * DIM);

    float acc[4][4][4];
#pragma unroll
    for (int mt = 0; mt < 4; mt++)
#pragma unroll
        for (int nt = 0; nt < 4; nt++)
#pragma unroll
            for (int i = 0; i < 4; i++) acc[mt][nt][i] = 0.f;

    {
#pragma unroll
        for (int i = 0; i < 8; i++) {
            int t = i >> 2;
            int e = (i & 3) * 256 + tid;
            int row = e >> 3, c16 = e & 7;
            CP_ASYNC16(sb + t * TILE_B + row * TSTRIDE + c16 * 16,
                       srcs[t] + (size_t)row * (DIM * 2) + c16 * 16);
        }
        CP_COMMIT();
    }

    const int arow = lane & 15;
    const int acolh = (lane >> 4) * 16;
    const int browa = ((lane >> 4) << 3) + (lane & 7);
    const int bcolh = ((lane >> 3) & 1) * 16;

    for (int c = 0; c < NCHUNK; c++) {
        if (c + 1 < NCHUNK) {
            const int k0b = (c + 1) * 128;
            uint32_t d = sb + ((c + 1) & 1) * STAGE_B;
#pragma unroll
            for (int i = 0; i < 8; i++) {
                int t = i >> 2;
                int e = (i & 3) * 256 + tid;
                int row = e >> 3, c16 = e & 7;
                CP_ASYNC16(d + t * TILE_B + row * TSTRIDE + c16 * 16,
                           srcs[t] + (size_t)row * (DIM * 2) + k0b + c16 * 16);
            }
            CP_COMMIT();
            CP_WAIT1();
        } else {
            CP_WAIT0();
        }
        __syncthreads();

        const uint32_t stage = sb + (c & 1) * STAGE_B;
        const uint32_t sA = stage;
        const uint32_t sW = stage + TILE_B;

#pragma unroll
        for (int ks = 0; ks < 4; ks++) {
            const int acol = ks * 32 + acolh;
            uint32_t bh[8];
            {
                uint32_t boff = (uint32_t)((wn + browa) * TSTRIDE + ks * 32 + bcolh);
                ldsm4(bh,     sW + boff);
                ldsm4(bh + 4, sW + boff + 16 * TSTRIDE);
            }
#pragma unroll
            for (int mt = 0; mt < 4; mt++) {
                uint32_t ah[4];
                uint32_t off = (uint32_t)((wm + mt * 16 + arow) * TSTRIDE + acol);
                ldsm4(ah, sA + off);
#pragma unroll
                for (int nt = 0; nt < 4; nt++)
                    mma16816h(acc[mt][nt], ah, bh + nt * 2);
            }
        }
        __syncthreads();
    }

    const int r0 = lane >> 2;
    const int c0 = (lane & 3) * 2;
    if (z == 2 && Vout) {
        // V projection: write per-head fp16 directly ([h][S][80])
#pragma unroll
        for (int mt = 0; mt < 4; mt++) {
#pragma unroll
            for (int nt = 0; nt < 4; nt++) {
                int gm = m0 + wm + mt * 16 + r0;
                int gn = n0 + wn + nt * 8 + c0;
                float2 bv = *(const float2*)(bias + gn);
                int hh = gn / HD, dd = gn - hh * HD;
                size_t va = ((size_t)hh * S + gm) * HD + dd;
                *(uint32_t*)(Vout + va) =
                    pkh(acc[mt][nt][0] + bv.x, acc[mt][nt][1] + bv.y);
                *(uint32_t*)(Vout + va + (size_t)8 * HD) =
                    pkh(acc[mt][nt][2] + bv.x, acc[mt][nt][3] + bv.y);
            }
        }
    } else {
#pragma unroll
        for (int mt = 0; mt < 4; mt++) {
#pragma unroll
            for (int nt = 0; nt < 4; nt++) {
                int gm = m0 + wm + mt * 16 + r0;
                int gn = n0 + wn + nt * 8 + c0;
                float2 bv = *(const float2*)(bias + gn);
                float2 o0, o1;
                o0.x = acc[mt][nt][0] + bv.x;
                o0.y = acc[mt][nt][1] + bv.y;
                o1.x = acc[mt][nt][2] + bv.x;
                o1.y = acc[mt][nt][3] + bv.y;
                *(float2*)(C + (size_t)gm * DIM + gn) = o0;
                *(float2*)(C + (size_t)(gm + 8) * DIM + gn) = o1;
            }
        }
    }
}

// ---------------- pack: rope + scale + per-head relayout (q, k only) --------
__global__ void pack_qkv(const float* __restrict__ cosb,
                         const float* __restrict__ sinb)
{
    const int s = blockIdx.x;
    const int tid = threadIdx.x;
    const float scale = 0.11180339887498949f;

    for (int p = tid; p < NH * 20; p += 256) {
        int h = p / 20, dp = (p % 20) * 2;
        float2 c2 = *(const float2*)(cosb + s * HD + dp);
        float2 s2 = *(const float2*)(sinb + s * HD + dp);
        size_t ib = (size_t)s * DIM + h * HD + dp;
        size_t ob = ((size_t)h * S + s) * HD + dp;

        float2 qa = *(const float2*)(g_q + ib);
        float2 qb = *(const float2*)(g_q + ib + 40);
        *(uint32_t*)(g_qh + ob) = pkh((qa.x * c2.x - qb.x * s2.x) * scale,
                                      (qa.y * c2.y - qb.y * s2.y) * scale);
        *(uint32_t*)(g_qh + ob + 40) = pkh((qb.x * c2.x + qa.x * s2.x) * scale,
                                           (qb.y * c2.y + qa.y * s2.y) * scale);

        float2 ka = *(const float2*)(g_k + ib);
        float2 kb = *(const float2*)(g_k + ib + 40);
        *(uint32_t*)(g_kh + ob)      = pkh(ka.x * c2.x - kb.x * s2.x,
                                           ka.y * c2.y - kb.y * s2.y);
        *(uint32_t*)(g_kh + ob + 40) = pkh(kb.x * c2.x + ka.x * s2.x,
                                           kb.y * c2.y + ka.y * s2.y);
    }
}

// ---------------- flash attention: fp16, 2 barriers/chunk, depth-1 prefetch -
#define ATS 176
#define ATB (64 * ATS)               // 11264
#define AQ  0
#define AK0 ATB
#define AV0 (2 * ATB)
#define AK1 (3 * ATB)
#define AV1 (4 * ATB)
#define APMAX (5 * ATB)
#define APLS  (APMAX + 512)
#define ATTN_SMEM (APLS + 256)       // 57088 B

__global__ __launch_bounds__(256, 2) void attn_mma(__half* __restrict__ ch)
{
    extern __shared__ char sm[];
    const uint32_t sb = smem_u32(sm);
    const int tid = threadIdx.x;
    const int wid = tid >> 5;
    const int lane = tid & 31;

    const int qt = blockIdx.x;
    const int h  = blockIdx.y;
    const int sg = blockIdx.z;
    const int s0 = sg * SEG;
    const int q0 = s0 + qt * 64;
    const size_t hb = (size_t)h * S * HD;

    const int wm = (wid & 3) * 16;
    const int wh = wid >> 2;
    const int wn = wh * 32;

    float* pmax = (float*)(sm + APMAX);
    float* plsum = (float*)(sm + APLS);

    const char* qhp = (const char*)(g_qh + hb + (size_t)q0 * HD);
    const char* khp = (const char*)(g_kh + hb + (size_t)s0 * HD);
    const char* vhp = (const char*)(g_vh + hb + (size_t)s0 * HD);

    auto cp_tile = [&](uint32_t dst, const char* src, int rb) {
#pragma unroll
        for (int i = 0; i < 3; i++) {
            int f = i * 256 + tid;
            if (f < 640) {
                int r = f / 10, c = f - r * 10;
                CP_ASYNC16(sb + dst + r * ATS + c * 16,
                           src + (size_t)(rb + r) * 160 + c * 16);
            }
        }
    };

    // prologue: Q + K0 + V0 in one group
    cp_tile(AQ, qhp, 0);
    cp_tile(AK0, khp, 0);
    cp_tile(AV0, vhp, 0);
    CP_COMMIT();

    float acc[10][4];
#pragma unroll
    for (int nt = 0; nt < 10; nt++)
#pragma unroll
        for (int i = 0; i < 4; i++) acc[nt][i] = 0.f;

    float mold0 = -1e30f, mold1 = -1e30f;
    float lsum0 = 0.f, lsum1 = 0.f;

    const int qrow = wm + (lane & 15);
    const uint32_t qcoloff = (uint32_t)((lane >> 4) * 16);
    const int krowa = wn + ((lane >> 4) << 3) + (lane & 7);
    const uint32_t kcoloff = (uint32_t)(((lane >> 3) & 1) * 16);
    const int r4 = lane >> 2;
    const int q2 = (lane & 3) * 2;

    for (int c = 0; c < 8; c++) {
        const uint32_t sKH = sb + ((c & 1) ? AK1 : AK0);
        const uint32_t sVH = sb + ((c & 1) ? AV1 : AV0);

        CP_WAIT0();
        __syncthreads();               // KV_c visible; PV_{c-1} drained block-wide

        if (c + 1 < 8) {               // refill opposite buffer (safe post-barrier)
            cp_tile((c & 1) ? AK0 : AK1, khp, (c + 1) * 64);
            cp_tile((c & 1) ? AV0 : AV1, vhp, (c + 1) * 64);
            CP_COMMIT();
        }

        // ---- S = Q K^T (fp16) ----
        float sa[4][4];
#pragma unroll
        for (int nt = 0; nt < 4; nt++)
#pragma unroll
            for (int i = 0; i < 4; i++) sa[nt][i] = 0.f;

#pragma unroll
        for (int ks = 0; ks < 5; ks++) {
            uint32_t qh4[4], kh[8];
            uint32_t qoff = (uint32_t)(qrow * ATS + ks * 32) + qcoloff;
            ldsm4(qh4, sb + AQ + qoff);
            uint32_t koff0 = (uint32_t)(krowa * ATS + ks * 32) + kcoloff;
            ldsm4(kh,     sKH + koff0);
            ldsm4(kh + 4, sKH + koff0 + 16 * ATS);
#pragma unroll
            for (int nt = 0; nt < 4; nt++)
                mma16816h(sa[nt], qh4, kh + nt * 2);
        }

        float mx0 = fmaxf(fmaxf(sa[0][0], sa[0][1]), fmaxf(sa[1][0], sa[1][1]));
        mx0 = fmaxf(mx0, fmaxf(fmaxf(sa[2][0], sa[2][1]), fmaxf(sa[3][0], sa[3][1])));
        float mx1 = fmaxf(fmaxf(sa[0][2], sa[0][3]), fmaxf(sa[1][2], sa[1][3]));
        mx1 = fmaxf(mx1, fmaxf(fmaxf(sa[2][2], sa[2][3]), fmaxf(sa[3][2], sa[3][3])));
        mx0 = fmaxf(mx0, __shfl_xor_sync(0xffffffffu, mx0, 1));
        mx0 = fmaxf(mx0, __shfl_xor_sync(0xffffffffu, mx0, 2));
        mx1 = fmaxf(mx1, __shfl_xor_sync(0xffffffffu, mx1, 1));
        mx1 = fmaxf(mx1, __shfl_xor_sync(0xffffffffu, mx1, 2));
        if ((lane & 3) == 0) {
            pmax[wh * 64 + wm + r4] = mx0;
            pmax[wh * 64 + wm + 8 + r4] = mx1;
        }

        __syncthreads();               // pmax visible

        float ma0 = fmaxf(pmax[wm + r4], pmax[64 + wm + r4]);
        float ma1 = fmaxf(pmax[wm + 8 + r4], pmax[64 + wm + 8 + r4]);
        float mn0 = fmaxf(mold0, ma0);
        float mn1 = fmaxf(mold1, ma1);
        float fs0 = __expf(mold0 - mn0);
        float fs1 = __expf(mold1 - mn1);
        mold0 = mn0; mold1 = mn1;

        float s0r = 0.f, s1r = 0.f;
#pragma unroll
        for (int nt = 0; nt < 4; nt++) {
            sa[nt][0] = __expf(sa[nt][0] - mn0);
            sa[nt][1] = __expf(sa[nt][1] - mn0);
            sa[nt][2] = __expf(sa[nt][2] - mn1);
            sa[nt][3] = __expf(sa[nt][3] - mn1);
            s0r += sa[nt][0] + sa[nt][1];
            s1r += sa[nt][2] + sa[nt][3];
        }
        s0r += __shfl_xor_sync(0xffffffffu, s0r, 1);
        s0r += __shfl_xor_sync(0xffffffffu, s0r, 2);
        s1r += __shfl_xor_sync(0xffffffffu, s1r, 1);
        s1r += __shfl_xor_sync(0xffffffffu, s1r, 2);
        lsum0 = lsum0 * fs0 + s0r;
        lsum1 = lsum1 * fs1 + s1r;

#pragma unroll
        for (int nt = 0; nt < 10; nt++) {
            acc[nt][0] *= fs0; acc[nt][1] *= fs0;
            acc[nt][2] *= fs1; acc[nt][3] *= fs1;
        }

#pragma unroll
        for (int kb = 0; kb < 2; kb++) {
            uint32_t aH[4];
            aH[0] = pkh(sa[2 * kb][0], sa[2 * kb][1]);
            aH[1] = pkh(sa[2 * kb][2], sa[2 * kb][3]);
            aH[2] = pkh(sa[2 * kb + 1][0], sa[2 * kb + 1][1]);
            aH[3] = pkh(sa[2 * kb + 1][2], sa[2 * kb + 1][3]);
            const int vrow = wn + kb * 16 + (lane & 15);
#pragma unroll
            for (int np = 0; np < 5; np++) {
                uint32_t vh4[4];
                uint32_t voff = (uint32_t)(vrow * ATS + (np * 16 + ((lane >> 4) << 3)) * 2);
                ldsm4t(vh4, sVH + voff);
                mma16816h(acc[np * 2], aH, vh4);
                mma16816h(acc[np * 2 + 1], aH, vh4 + 2);
            }
        }
    }

    // ---- epilogue: combine column halves, normalize, write ctx fp16 --------
    float* cb = (float*)(sm + AK0);
    if (wh == 1) {
#pragma unroll
        for (int nt = 0; nt < 10; nt++) {
            int cc = nt * 8 + q2;
            cb[(wm + r4) * 80 + cc]     = acc[nt][0];
            cb[(wm + r4) * 80 + cc + 1] = acc[nt][1];
            cb[(wm + r4 + 8) * 80 + cc]     = acc[nt][2];
            cb[(wm + r4 + 8) * 80 + cc + 1] = acc[nt][3];
        }
        if ((lane & 3) == 0) {
            plsum[wm + r4] = lsum0;
            plsum[wm + r4 + 8] = lsum1;
        }
    }
    __syncthreads();
    if (wh == 0) {
        float li0 = 1.f / (lsum0 + plsum[wm + r4]);
        float li1 = 1.f / (lsum1 + plsum[wm + r4 + 8]);
        int gr0 = q0 + wm + r4;
#pragma unroll
        for (int nt = 0; nt < 10; nt++) {
            int col = h * HD + nt * 8 + q2;
            float x0 = (acc[nt][0] + cb[(wm + r4) * 80 + nt * 8 + q2]) * li0;
            float y0 = (acc[nt][1] + cb[(wm + r4) * 80 + nt * 8 + q2 + 1]) * li0;
            float x1 = (acc[nt][2] + cb[(wm + r4 + 8) * 80 + nt * 8 + q2]) * li1;
            float y1 = (acc[nt][3] + cb[(wm + r4 + 8) * 80 + nt * 8 + q2 + 1]) * li1;
            size_t a0 = (size_t)gr0 * DIM + col;
            size_t a1 = a0 + (size_t)8 * DIM;
            *(uint32_t*)(ch + a0) = pkh(x0, y0);
            *(uint32_t*)(ch + a1) = pkh(x1, y1);
        }
    }
}

// ---------------------------------------------------------------------------
extern "C" void kernel_launch(void* const* d_in, const int* in_sizes, int n_in,
                              void* d_out, int out_size)
{
    const float* hs   = (const float*)d_in[0];
    const float* cosb = (const float*)d_in[1];
    const float* sinb = (const float*)d_in[2];
    const float* wq   = (const float*)d_in[3];
    const float* bq   = (const float*)d_in[4];
    const float* wk   = (const float*)d_in[5];
    const float* bk   = (const float*)d_in[6];
    const float* wv   = (const float*)d_in[7];
    const float* bv   = (const float*)d_in[8];
    const float* wo   = (const float*)d_in[9];
    const float* bo   = (const float*)d_in[10];
    float* out = (float*)d_out;

    float *qp, *kp;
    cudaGetSymbolAddress((void**)&qp, g_q);
    cudaGetSymbolAddress((void**)&kp, g_k);
    __half *ah, *wh, *ch, *vh;
    cudaGetSymbolAddress((void**)&ah, g_ah);
    cudaGetSymbolAddress((void**)&wh, g_wh);
    cudaGetSymbolAddress((void**)&ch, g_ch);
    cudaGetSymbolAddress((void**)&vh, g_vh);

    cudaFuncSetAttribute(gemm_hmma,
                         cudaFuncAttributeMaxDynamicSharedMemorySize, GEMM_SMEM);
    cudaFuncSetAttribute(attn_mma,
                         cudaFuncAttributeMaxDynamicSharedMemorySize, ATTN_SMEM);

    // 1) all fp32->fp16 conversions, one launch
    split_all<<<(HS4 + 4 * W4) / 256, 256>>>(
        (const float4*)hs, (const float4*)wq, (const float4*)wk,
        (const float4*)wv, (const float4*)wo, (uint2*)ah, (uint2*)wh);

    // 2) QKV projections (V written directly to per-head fp16)
    gemm_hmma<<<dim3(DIM / GBN, S / GBM, 3), 256, GEMM_SMEM>>>(
        ah, wh, 0, bq, bk, bv, qp, kp, vh);

    // 3) rope + scale + per-head pack (q, k)
    pack_qkv<<<S, 256>>>(cosb, sinb);

    // 4) attention
    attn_mma<<<dim3(8, NH, NSEG), 256, ATTN_SMEM>>>(ch);

    // 5) O projection
    gemm_hmma<<<dim3(DIM / GBN, S / GBM, 1), 256, GEMM_SMEM>>>(
        ch, wh, 3, bo, bo, bo, out, out, nullptr);
}